// round 11
// baseline (speedup 1.0000x reference)
#include <cuda_runtime.h>
#include <cstdint>

#define B_   4
#define S_   2048
#define D_   512
#define H_   8
#define DK_  64

// ---------------------------------------------------------------------------
// Scratch (allocation-free: __device__ globals)
// kfmt tile arrays: tile index layout noted per array.
// ---------------------------------------------------------------------------
__device__ uint32_t g_Qhi[B_*H_*S_*DK_];   // [(b*H+h)*32 + stile][4096]
__device__ uint32_t g_Qlo[B_*H_*S_*DK_];
__device__ uint32_t g_Khi[B_*H_*S_*DK_];
__device__ uint32_t g_Klo[B_*H_*S_*DK_];
__device__ uint32_t g_Vt [B_*H_*S_*DK_];   // transposed (rows = dk, k = s)
__device__ uint32_t g_OcT[B_*S_*D_];       // attn out, kfmt: [mtile(128)*8 + kchunk][4096]
__device__ uint32_t g_Whi[3*8*8*4096];     // [(which*8+h)*8 + c][4096]
__device__ uint32_t g_Wlo[3*8*8*4096];
__device__ uint32_t g_WOt[8*8*4096];       // [c*8 + ntile][4096]

// ===========================================================================
// mma.sync tf32 helpers (baseline PTX, works on compute_103 target)
// ===========================================================================
__device__ __forceinline__ uint32_t f2tf32(float x) {
    uint32_t r; asm("cvt.rna.tf32.f32 %0, %1;" : "=r"(r) : "f"(x)); return r;
}
__device__ __forceinline__ void mma8(float* d,
                                     uint32_t a0, uint32_t a1, uint32_t a2, uint32_t a3,
                                     uint32_t b0, uint32_t b1) {
    asm volatile("mma.sync.aligned.m16n8k8.row.col.f32.tf32.tf32.f32 "
                 "{%0,%1,%2,%3}, {%4,%5,%6,%7}, {%8,%9}, {%0,%1,%2,%3};"
                 : "+f"(d[0]), "+f"(d[1]), "+f"(d[2]), "+f"(d[3])
                 : "r"(a0), "r"(a1), "r"(a2), "r"(a3), "r"(b0), "r"(b1));
}
__device__ __forceinline__ void cp16(uint32_t saddr, const void* g) {
    asm volatile("cp.async.cg.shared.global [%0], [%1], 16;" :: "r"(saddr), "l"(g) : "memory");
}
#define CP_COMMIT() asm volatile("cp.async.commit_group;" ::: "memory")
__device__ __forceinline__ uint32_t smem_u32(const void* p) {
    uint32_t a;
    asm("{ .reg .u64 t; cvta.to.shared.u64 t, %1; cvt.u32.u64 %0, t; }" : "=r"(a) : "l"(p));
    return a;
}

// kfmt, per 64x64 tile: word(row,k) = (ks*64+row)*8 + pos(kin)^sw,
//   ks=k>>3, kin=k&7, pos(kin) = (kin&3)*2 + (kin>>2),
//   sw = 4*(((row>>2)^(ks>>2))&1). Fragment (kin=t,t+4) = LDS.64 at 2t^sw.

// ---------------------------------------------------------------------------
// Transposed-gather loaders (used by prep kernel): B tile rows = n, k = rows.
// ---------------------------------------------------------------------------
__device__ __forceinline__ void ldg_T(const float* __restrict__ bsrc, int ldb,
                                      int tid, float wst[4][8])
{
    const int n = tid & 63, kh = tid >> 6;
    #pragma unroll
    for (int j = 0; j < 4; j++) {
        const int ks = kh * 4 + j;
        #pragma unroll
        for (int si = 0; si < 8; si++)
            wst[j][si] = bsrc[(size_t)(ks * 8 + si) * ldb + n];
    }
}
__device__ __forceinline__ void sts_T_split(const float wst[4][8],
                                            uint32_t* __restrict__ smw,
                                            int whi, int wlo, int tid)
{
    const int n = tid & 63, kh = tid >> 6;
    #pragma unroll
    for (int j = 0; j < 4; j++) {
        const int ks = kh * 4 + j;
        uint32_t h[8], l[8];
        #pragma unroll
        for (int e = 0; e < 8; e++) {
            h[e] = __float_as_uint(wst[j][e]) & 0xFFFFE000u;
            l[e] = f2tf32(wst[j][e] - __uint_as_float(h[e]));
        }
        const int sw = 4 * (((n >> 2) ^ (ks >> 2)) & 1);
        const uint32_t base = (uint32_t)((ks * 64 + n) * 8);
        *(uint4*)(smw + whi + base + (0 ^ sw)) = make_uint4(h[0], h[4], h[1], h[5]);
        *(uint4*)(smw + whi + base + (4 ^ sw)) = make_uint4(h[2], h[6], h[3], h[7]);
        *(uint4*)(smw + wlo + base + (0 ^ sw)) = make_uint4(l[0], l[4], l[1], l[5]);
        *(uint4*)(smw + wlo + base + (4 ^ sw)) = make_uint4(l[2], l[6], l[3], l[7]);
    }
}
__device__ __forceinline__ void sts_T_single(const float wst[4][8],
                                             uint32_t* __restrict__ smw,
                                             int whi, int tid)
{
    const int n = tid & 63, kh = tid >> 6;
    #pragma unroll
    for (int j = 0; j < 4; j++) {
        const int ks = kh * 4 + j;
        uint32_t h[8];
        #pragma unroll
        for (int e = 0; e < 8; e++) h[e] = f2tf32(wst[j][e]);
        const int sw = 4 * (((n >> 2) ^ (ks >> 2)) & 1);
        const uint32_t base = (uint32_t)((ks * 64 + n) * 8);
        *(uint4*)(smw + whi + base + (0 ^ sw)) = make_uint4(h[0], h[4], h[1], h[5]);
        *(uint4*)(smw + whi + base + (4 ^ sw)) = make_uint4(h[2], h[6], h[3], h[7]);
    }
}

// ===========================================================================
// prep_w: preformat weights into kfmt. grid (8 chunks, 8 h/ntile, 4), 128 thr.
// z=0..2: WQ/WK/WV split; z=3: WO single.
// ===========================================================================
__global__ __launch_bounds__(128) void prep_w_kernel(const float* __restrict__ WQ,
                                                     const float* __restrict__ WK,
                                                     const float* __restrict__ WV,
                                                     const float* __restrict__ WO)
{
    __shared__ uint32_t smw[8192];
    const int tid = threadIdx.x;
    const int c  = blockIdx.x;
    const int hn = blockIdx.y;
    const int which = blockIdx.z;
    float wst[4][8];
    if (which < 3) {
        const float* W = (which == 0) ? WQ : (which == 1) ? WK : WV;
        const float* src = W + (size_t)hn * (D_ * DK_) + (size_t)c * 64 * DK_;
        ldg_T(src, DK_, tid, wst);
        sts_T_split(wst, smw, 0, 4096, tid);
        __syncthreads();
        uint32_t* dH = g_Whi + ((size_t)(which * 8 + hn) * 8 + c) * 4096;
        uint32_t* dL = g_Wlo + ((size_t)(which * 8 + hn) * 8 + c) * 4096;
        for (int i = tid; i < 1024; i += 128) {
            ((uint4*)dH)[i] = ((const uint4*)smw)[i];
            ((uint4*)dL)[i] = ((const uint4*)smw)[1024 + i];
        }
    } else {
        const float* src = WO + (size_t)c * 64 * D_ + hn * 64;
        ldg_T(src, D_, tid, wst);
        sts_T_single(wst, smw, 0, tid);
        __syncthreads();
        uint32_t* dW = g_WOt + ((size_t)(c * 8 + hn)) * 4096;
        for (int i = tid; i < 1024; i += 128)
            ((uint4*)dW)[i] = ((const uint4*)smw)[i];
    }
}

// ===========================================================================
// Projection GEMM: m-tile 256 (4 subtiles), 256 thr / 8 warps, m32/warp, N=64.
// A converted in-kernel (reg-staged); B streamed via cp.async (preformatted).
// All three projections use split (3-term) A*W.
// Q/K outputs: split kfmt.  V output: single tf32, transposed kfmt.
// smem words: Ahi [0,16384) | Alo [16384,32768) | B0 [32768,40960) | B1 [40960,49152)
// ===========================================================================
#define PJ_ALO 16384
#define PJ_B0  32768
#define PJ_BSZ 8192
#define PJ_WORDS 49152   // 192 KB

__global__ void __launch_bounds__(256, 1) proj_mma_kernel(const float* __restrict__ Qx,
                                                          const float* __restrict__ Kx,
                                                          const float* __restrict__ Vx)
{
    extern __shared__ uint32_t smw[];
    const uint32_t sbase = smem_u32(smw);

    const int which = blockIdx.z;
    const float* __restrict__ X = (which == 0) ? Qx : (which == 1) ? Kx : Vx;

    const int tid  = threadIdx.x;
    const int lane = tid & 31;
    const int w    = tid >> 5;           // 0..7
    const int g    = lane >> 2;
    const int t    = lane & 3;
    const int g2   = (g >> 2) & 1;
    const int ts   = w >> 1;             // A subtile 0..3
    const int rA0  = (w & 1) * 32 + g;   // base row within subtile
    const int pe = ((2 * t) & 3) * 2 + (t >> 1);
    const int po = ((2 * t + 1) & 3) * 2 + ((2 * t + 1) >> 2);

    const int h  = blockIdx.x;
    const int m0 = blockIdx.y * 256;
    const float* __restrict__ Xm = X + (size_t)m0 * D_;
    const uint32_t* __restrict__ Bh = g_Whi + (size_t)(which * 8 + h) * 8 * 4096;
    const uint32_t* __restrict__ Bl = g_Wlo + (size_t)(which * 8 + h) * 8 * 4096;

    float acc[2][8][4];
    #pragma unroll
    for (int mg = 0; mg < 2; mg++)
        #pragma unroll
        for (int nt = 0; nt < 8; nt++)
            #pragma unroll
            for (int j = 0; j < 4; j++) acc[mg][nt][j] = 0.f;

    // stage A chunk 0 (thread owns full row tid of the chunk)
    float4 xs[16];
    #pragma unroll
    for (int i = 0; i < 16; i++)
        xs[i] = *(const float4*)(Xm + (size_t)tid * D_ + i * 4);

    // prologue: B chunk 0 into buf 0
    {
        const uint4* sh = (const uint4*)(Bh);
        const uint4* sl = (const uint4*)(Bl);
        const uint32_t db = sbase + PJ_B0 * 4;
        #pragma unroll
        for (int i = 0; i < 4; i++) {
            const int idx = tid + i * 256;
            cp16(db + idx * 16,            sh + idx);
            cp16(db + 4096 * 4 + idx * 16, sl + idx);
        }
        CP_COMMIT();
    }

    const int sr  = tid & 63;    // STS row within subtile
    const int ssub = tid >> 6;

    for (int c = 0; c < 8; c++) {
        const int bb = c & 1;

        // --- convert + STS A chunk c from regs ---
        #pragma unroll
        for (int ks = 0; ks < 8; ks++) {
            float x[8] = {xs[ks*2].x, xs[ks*2].y, xs[ks*2].z, xs[ks*2].w,
                          xs[ks*2+1].x, xs[ks*2+1].y, xs[ks*2+1].z, xs[ks*2+1].w};
            uint32_t hh[8], ll[8];
            #pragma unroll
            for (int e = 0; e < 8; e++) {
                hh[e] = __float_as_uint(x[e]) & 0xFFFFE000u;
                ll[e] = f2tf32(x[e] - __uint_as_float(hh[e]));
            }
            const int sw = 4 * (((sr >> 2) ^ (ks >> 2)) & 1);
            const uint32_t base = (uint32_t)(ssub * 4096 + (ks * 64 + sr) * 8);
            *(uint4*)(smw + base + (0 ^ sw)) = make_uint4(hh[0], hh[4], hh[1], hh[5]);
            *(uint4*)(smw + base + (4 ^ sw)) = make_uint4(hh[2], hh[6], hh[3], hh[7]);
            *(uint4*)(smw + PJ_ALO + base + (0 ^ sw)) = make_uint4(ll[0], ll[4], ll[1], ll[5]);
            *(uint4*)(smw + PJ_ALO + base + (4 ^ sw)) = make_uint4(ll[2], ll[6], ll[3], ll[7]);
        }

        if (c < 7) {
            // stage A chunk c+1
            #pragma unroll
            for (int i = 0; i < 16; i++)
                xs[i] = *(const float4*)(Xm + (size_t)tid * D_ + (c + 1) * 64 + i * 4);
            // cp B chunk c+1 into alt buffer
            const uint4* sh = (const uint4*)(Bh + (size_t)(c + 1) * 4096);
            const uint4* sl = (const uint4*)(Bl + (size_t)(c + 1) * 4096);
            const uint32_t db = sbase + (PJ_B0 + (bb ^ 1) * PJ_BSZ) * 4;
            #pragma unroll
            for (int i = 0; i < 4; i++) {
                const int idx = tid + i * 256;
                cp16(db + idx * 16,            sh + idx);
                cp16(db + 4096 * 4 + idx * 16, sl + idx);
            }
            CP_COMMIT();
            asm volatile("cp.async.wait_group 1;" ::: "memory");
        } else {
            asm volatile("cp.async.wait_group 0;" ::: "memory");
        }
        __syncthreads();

        // --- MMA: split 3-term, m32 per warp ---
        const int bw = PJ_B0 + bb * PJ_BSZ;
        #pragma unroll
        for (int ks = 0; ks < 8; ks++) {
            const int off = 2 * t ^ (4 * (g2 ^ ((ks >> 2) & 1)));
            const uint32_t ab = (uint32_t)(ts * 4096);
            uint2 ah[4], al[4];
            #pragma unroll
            for (int q = 0; q < 4; q++) {
                const uint32_t ra = ab + (ks * 64 + rA0 + 8 * q) * 8 + off;
                ah[q] = *(const uint2*)(smw + ra);
                al[q] = *(const uint2*)(smw + PJ_ALO + ra);
            }
            #pragma unroll
            for (int nt = 0; nt < 8; nt++) {
                const uint32_t ba = (uint32_t)(bw + (ks * 64 + nt * 8 + g) * 8 + off);
                uint2 bhv = *(const uint2*)(smw + ba);
                uint2 blv = *(const uint2*)(smw + 4096 + ba);
                mma8(acc[0][nt], ah[0].x, ah[1].x, ah[0].y, ah[1].y, bhv.x, bhv.y);
                mma8(acc[0][nt], al[0].x, al[1].x, al[0].y, al[1].y, bhv.x, bhv.y);
                mma8(acc[0][nt], ah[0].x, ah[1].x, ah[0].y, ah[1].y, blv.x, blv.y);
                mma8(acc[1][nt], ah[2].x, ah[3].x, ah[2].y, ah[3].y, bhv.x, bhv.y);
                mma8(acc[1][nt], al[2].x, al[3].x, al[2].y, al[3].y, bhv.x, bhv.y);
                mma8(acc[1][nt], ah[2].x, ah[3].x, ah[2].y, ah[3].y, blv.x, blv.y);
            }
        }
        __syncthreads();
    }

    const int bb2 = m0 >> 11;
    const int st0 = (m0 & 2047) >> 6;

    if (which != 2) {
        // --- Q/K epilogue: split kfmt staged in smem, then linear copy ---
        #pragma unroll
        for (int mg = 0; mg < 2; mg++)
            #pragma unroll
            for (int nt = 0; nt < 8; nt++) {
                const int sw = 4 * (g2 ^ ((nt >> 2) & 1));
                #pragma unroll
                for (int j = 0; j < 2; j++) {
                    float p0 = acc[mg][nt][2 * j], p1 = acc[mg][nt][2 * j + 1];
                    uint32_t h0 = __float_as_uint(p0) & 0xFFFFE000u;
                    uint32_t h1 = __float_as_uint(p1) & 0xFFFFE000u;
                    uint32_t l0 = f2tf32(p0 - __uint_as_float(h0));
                    uint32_t l1 = f2tf32(p1 - __uint_as_float(h1));
                    const int rr = rA0 + 16 * mg + 8 * j;
                    const uint32_t base = (uint32_t)(ts * 4096 + (nt * 64 + rr) * 8);
                    smw[base + (pe ^ sw)] = h0;
                    smw[base + (po ^ sw)] = h1;
                    smw[PJ_ALO + base + (pe ^ sw)] = l0;
                    smw[PJ_ALO + base + (po ^ sw)] = l1;
                }
            }
        __syncthreads();
        uint32_t* dH = (which == 0 ? g_Qhi : g_Khi) + ((size_t)((bb2 * H_ + h) * 32 + st0)) * 4096;
        uint32_t* dL = (which == 0 ? g_Qlo : g_Klo) + ((size_t)((bb2 * H_ + h) * 32 + st0)) * 4096;
        for (int i = tid; i < 4096; i += 256) {
            ((uint4*)dH)[i] = ((const uint4*)smw)[i];
            ((uint4*)dL)[i] = ((const uint4*)smw)[4096 + i];
        }
    } else {
        // --- V epilogue: raw tf32 stage -> transpose -> kfmt Vt ---
        #pragma unroll
        for (int mg = 0; mg < 2; mg++)
            #pragma unroll
            for (int nt = 0; nt < 8; nt++)
                #pragma unroll
                for (int j = 0; j < 2; j++) {
                    const int rr = rA0 + 16 * mg + 8 * j;
                    smw[ts * 4096 + rr * 64 + nt * 8 + 2 * t]     = f2tf32(acc[mg][nt][2 * j]);
                    smw[ts * 4096 + rr * 64 + nt * 8 + 2 * t + 1] = f2tf32(acc[mg][nt][2 * j + 1]);
                }
        __syncthreads();
        {
            const int vt = tid >> 6, vdk = tid & 63;
            #pragma unroll
            for (int sc = 0; sc < 8; sc++) {
                uint32_t v[8];
                #pragma unroll
                for (int si = 0; si < 8; si++)
                    v[si] = smw[vt * 4096 + (sc * 8 + si) * 64 + vdk];
                const int sw = 4 * (((vdk >> 2) ^ (sc >> 2)) & 1);
                const uint32_t base = (uint32_t)(PJ_ALO + vt * 4096 + (sc * 64 + vdk) * 8);
                *(uint4*)(smw + base + (0 ^ sw)) = make_uint4(v[0], v[4], v[1], v[5]);
                *(uint4*)(smw + base + (4 ^ sw)) = make_uint4(v[2], v[6], v[3], v[7]);
            }
        }
        __syncthreads();
        uint32_t* dV = g_Vt + ((size_t)((bb2 * H_ + h) * 32 + st0)) * 4096;
        for (int i = tid; i < 4096; i += 256)
            ((uint4*)dV)[i] = ((const uint4*)smw)[4096 + i];
    }
}

// ===========================================================================
// Output GEMM: fully preformatted streaming. m-tile 256, 256 thr, m32/warp.
// smem words: A0 [0,16384) | A1 [16384,32768) | B0 [32768,36864) | B1 [36864,40960)
// ===========================================================================
#define OG_B0 32768
#define OG_WORDS 40960   // 160 KB

__global__ void __launch_bounds__(256, 1) out_mma_kernel(float* __restrict__ out)
{
    extern __shared__ uint32_t smw[];
    const uint32_t sbase = smem_u32(smw);

    const int tid  = threadIdx.x;
    const int lane = tid & 31;
    const int w    = tid >> 5;
    const int g    = lane >> 2;
    const int t    = lane & 3;
    const int g2   = (g >> 2) & 1;
    const int ts   = w >> 1;
    const int rA0  = (w & 1) * 32 + g;

    const int n0t = blockIdx.x;          // n-tile 0..7
    const int mt0 = blockIdx.y * 4;      // base A tile index

    float acc[2][8][4];
    #pragma unroll
    for (int mg = 0; mg < 2; mg++)
        #pragma unroll
        for (int nt = 0; nt < 8; nt++)
            #pragma unroll
            for (int j = 0; j < 4; j++) acc[mg][nt][j] = 0.f;

    // prologue: chunk 0
    {
        #pragma unroll
        for (int s = 0; s < 4; s++) {
            const uint4* sa = (const uint4*)(g_OcT + ((size_t)(mt0 + s) * 8 + 0) * 4096);
            const uint32_t da = sbase + (s * 4096) * 4;
            #pragma unroll
            for (int i = 0; i < 4; i++) {
                const int idx = tid + i * 256;
                cp16(da + idx * 16, sa + idx);
            }
        }
        const uint4* sb = (const uint4*)(g_WOt + ((size_t)(0 * 8 + n0t)) * 4096);
        const uint32_t db = sbase + OG_B0 * 4;
        cp16(db + tid * 16, sb + tid);
        cp16(db + (tid + 256) * 16, sb + tid + 256);
        cp16(db + (tid + 512) * 16, sb + tid + 512);
        cp16(db + (tid + 768) * 16, sb + tid + 768);
        CP_COMMIT();
    }

    for (int c = 0; c < 8; c++) {
        const int bb = c & 1;
        if (c < 7) {
            #pragma unroll
            for (int s = 0; s < 4; s++) {
                const uint4* sa = (const uint4*)(g_OcT + ((size_t)(mt0 + s) * 8 + (c + 1)) * 4096);
                const uint32_t da = sbase + ((bb ^ 1) * 16384 + s * 4096) * 4;
                #pragma unroll
                for (int i = 0; i < 4; i++) {
                    const int idx = tid + i * 256;
                    cp16(da + idx * 16, sa + idx);
                }
            }
            const uint4* sb = (const uint4*)(g_WOt + ((size_t)((c + 1) * 8 + n0t)) * 4096);
            const uint32_t db = sbase + (OG_B0 + (bb ^ 1) * 4096) * 4;
            #pragma unroll
            for (int i = 0; i < 4; i++) {
                const int idx = tid + i * 256;
                cp16(db + idx * 16, sb + idx);
            }
            CP_COMMIT();
            asm volatile("cp.async.wait_group 1;" ::: "memory");
        } else {
            asm volatile("cp.async.wait_group 0;" ::: "memory");
        }
        __syncthreads();

        const uint32_t aw = bb * 16384 + ts * 4096;
        const uint32_t bw = OG_B0 + bb * 4096;
        #pragma unroll
        for (int ks = 0; ks < 8; ks++) {
            const int off = 2 * t ^ (4 * (g2 ^ ((ks >> 2) & 1)));
            uint2 a[4];
            #pragma unroll
            for (int q = 0; q < 4; q++)
                a[q] = *(const uint2*)(smw + aw + (ks * 64 + rA0 + 8 * q) * 8 + off);
            #pragma unroll
            for (int nt = 0; nt < 8; nt++) {
                uint2 bv = *(const uint2*)(smw + bw + (ks * 64 + nt * 8 + g) * 8 + off);
                mma8(acc[0][nt], a[0].x, a[1].x, a[0].y, a[1].y, bv.x, bv.y);
                mma8(acc[1][nt], a[2].x, a[3].x, a[2].y, a[3].y, bv.x, bv.y);
            }
        }
        __syncthreads();
    }

    // epilogue: write fp32 rows
    const int m0 = mt0 * 64;
    #pragma unroll
    for (int mg = 0; mg < 2; mg++)
        #pragma unroll
        for (int j = 0; j < 2; j++) {
            const int m = m0 + ts * 64 + rA0 + 16 * mg + 8 * j;
            float* dst = out + (size_t)m * D_ + n0t * 64;
            #pragma unroll
            for (int nt = 0; nt < 8; nt++)
                *(float2*)(dst + nt * 8 + t * 2) =
                    make_float2(acc[mg][nt][2 * j], acc[mg][nt][2 * j + 1]);
        }
}

// ===========================================================================
// Flash attention: CTA = (b, h, 128 q-rows), 256 thr. (R9 core, new epilogue)
// smem words: buf0 [KHI 0 | KLO 4096 | VT 8192], buf1 +12288, PS 24576 (2 tiles)
// ===========================================================================
#define ABUF 12288
#define APS  24576
#define ASMEM_WORDS 32768   // 128 KB

__global__ void __launch_bounds__(256, 1) attn_mma_kernel()
{
    extern __shared__ uint32_t smw[];
    const uint32_t sbase = smem_u32(smw);

    const int tid  = threadIdx.x;
    const int lane = tid & 31;
    const int w    = tid >> 5;
    const int g    = lane >> 2;
    const int t    = lane & 3;
    const int g2   = (g >> 2) & 1;
    const int row0 = w * 16 + g;
    const int offA = 2 * t ^ (4 * g2);
    const int pe = ((2 * t) & 3) * 2 + (t >> 1);
    const int po = ((2 * t + 1) & 3) * 2 + ((2 * t + 1) >> 2);

    const int h  = blockIdx.y;
    const int b  = blockIdx.z;
    const size_t kvbase = ((size_t)(b * H_ + h)) * 32 * 4096;

    {
        const uint4* sK = (const uint4*)(g_Khi + kvbase);
        const uint4* sL = (const uint4*)(g_Klo + kvbase);
        const uint4* sV = (const uint4*)(g_Vt  + kvbase);
        #pragma unroll
        for (int k = 0; k < 4; k++) {
            const int i = tid + k * 256;
            cp16(sbase + i * 16,          sK + i);
            cp16(sbase + 16384 + i * 16,  sL + i);
            cp16(sbase + 32768 + i * 16,  sV + i);
        }
        CP_COMMIT();
    }

    uint2 qh0[8], qh1[8], ql0[8], ql1[8];
    {
        const int qst = blockIdx.x * 2 + (row0 >> 6);
        const size_t qtb = ((size_t)(b * H_ + h) * 32 + qst) * 4096;
        const int r = row0 & 63;
        #pragma unroll
        for (int ks = 0; ks < 8; ks++) {
            const int off = offA ^ (4 * ((ks >> 2) & 1));
            const size_t i0 = qtb + (ks * 64 + r) * 8 + off;
            const size_t i1 = qtb + (ks * 64 + r + 8) * 8 + off;
            qh0[ks] = *(const uint2*)(g_Qhi + i0);
            qh1[ks] = *(const uint2*)(g_Qhi + i1);
            ql0[ks] = *(const uint2*)(g_Qlo + i0);
            ql1[ks] = *(const uint2*)(g_Qlo + i1);
        }
    }

    float o[8][4];
    #pragma unroll
    for (int nt = 0; nt < 8; nt++)
        #pragma unroll
        for (int j = 0; j < 4; j++) o[nt][j] = 0.f;
    float mrun[2] = {-1e30f, -1e30f}, lrun[2] = {0.f, 0.f};
    const float Cc = 0.125f * 1.4426950408889634f;

    const int ptile = APS + (row0 >> 6) * 4096;
    const int pr    = row0 & 63;

    for (int it = 0; it < 32; it++) {
        const int cur = it & 1;

        if (it < 31) {
            const uint32_t db = sbase + (cur ^ 1) * (ABUF * 4);
            const size_t tb = kvbase + (size_t)(it + 1) * 4096;
            const uint4* sK = (const uint4*)(g_Khi + tb);
            const uint4* sL = (const uint4*)(g_Klo + tb);
            const uint4* sV = (const uint4*)(g_Vt  + tb);
            #pragma unroll
            for (int k = 0; k < 4; k++) {
                const int i = tid + k * 256;
                cp16(db + i * 16,          sK + i);
                cp16(db + 16384 + i * 16,  sL + i);
                cp16(db + 32768 + i * 16,  sV + i);
            }
            CP_COMMIT();
            asm volatile("cp.async.wait_group 1;" ::: "memory");
        } else {
            asm volatile("cp.async.wait_group 0;" ::: "memory");
        }
        __syncthreads();

        const int bk = cur * ABUF;

        float accS[8][4];
        #pragma unroll
        for (int nt = 0; nt < 8; nt++)
            #pragma unroll
            for (int j = 0; j < 4; j++) accS[nt][j] = 0.f;

        #pragma unroll
        for (int ks = 0; ks < 8; ks++) {
            const int off = offA ^ (4 * ((ks >> 2) & 1));
            #pragma unroll
            for (int nt = 0; nt < 8; nt++) {
                const uint32_t ba = (uint32_t)(bk + (ks * 64 + nt * 8 + g) * 8 + off);
                uint2 bh = *(const uint2*)(smw + ba);
                uint2 bl = *(const uint2*)(smw + 4096 + ba);
                mma8(accS[nt], qh0[ks].x, qh1[ks].x, qh0[ks].y, qh1[ks].y, bh.x, bh.y);
                mma8(accS[nt], ql0[ks].x, ql1[ks].x, ql0[ks].y, ql1[ks].y, bh.x, bh.y);
                mma8(accS[nt], qh0[ks].x, qh1[ks].x, qh0[ks].y, qh1[ks].y, bl.x, bl.y);
            }
        }

        #pragma unroll
        for (int j = 0; j < 2; j++) {
            float m = -1e30f;
            #pragma unroll
            for (int nt = 0; nt < 8; nt++)
                m = fmaxf(m, fmaxf(accS[nt][2 * j], accS[nt][2 * j + 1]));
            m = fmaxf(m, __shfl_xor_sync(0xffffffffu, m, 1));
            m = fmaxf(m, __shfl_xor_sync(0xffffffffu, m, 2));

            float mnew = fmaxf(mrun[j], m);
            float scl  = exp2f((mrun[j] - mnew) * Cc);
            mrun[j] = mnew;

            const int prow = pr + 8 * j;
            float sum = 0.f;
            #pragma unroll
            for (int nt = 0; nt < 8; nt++) {
                float p0 = exp2f((accS[nt][2 * j]     - mnew) * Cc);
                float p1 = exp2f((accS[nt][2 * j + 1] - mnew) * Cc);
                sum += p0 + p1;
                const int sw = 4 * ((g2 ^ (nt >> 2)) & 1);
                const uint32_t base = (uint32_t)(ptile + (nt * 64 + prow) * 8);
                smw[base + (pe ^ sw)] = f2tf32(p0);
                smw[base + (po ^ sw)] = f2tf32(p1);
                o[nt][2 * j]     *= scl;
                o[nt][2 * j + 1] *= scl;
            }
            sum += __shfl_xor_sync(0xffffffffu, sum, 1);
            sum += __shfl_xor_sync(0xffffffffu, sum, 2);
            lrun[j] = lrun[j] * scl + sum;
        }
        __syncwarp();

        #pragma unroll
        for (int ks = 0; ks < 8; ks++) {
            const int off = offA ^ (4 * ((ks >> 2) & 1));
            uint2 p0 = *(const uint2*)(smw + ptile + (ks * 64 + pr) * 8 + off);
            uint2 p1 = *(const uint2*)(smw + ptile + (ks * 64 + pr + 8) * 8 + off);
            #pragma unroll
            for (int nt = 0; nt < 8; nt++) {
                uint2 bv = *(const uint2*)(smw + bk + 8192 + (ks * 64 + nt * 8 + g) * 8 + off);
                mma8(o[nt], p0.x, p1.x, p0.y, p1.y, bv.x, bv.y);
            }
        }
        __syncthreads();
    }

    // --- Epilogue: normalize, write kfmt tf32 tiles into g_OcT ---
    {
        const int stl = row0 >> 6;        // local tile 0/1
        const int rr0 = row0 & 63;
        #pragma unroll
        for (int j = 0; j < 2; j++) {
            const float inv = 1.f / lrun[j];
            const int rr = rr0 + 8 * j;
            #pragma unroll
            for (int nt = 0; nt < 8; nt++) {
                const int sw = 4 * (g2 ^ ((nt >> 2) & 1));
                const uint32_t base = (uint32_t)(APS + stl * 4096 + (nt * 64 + rr) * 8);
                smw[base + (pe ^ sw)] = f2tf32(o[nt][2 * j] * inv);
                smw[base + (po ^ sw)] = f2tf32(o[nt][2 * j + 1] * inv);
            }
        }
        __syncthreads();
        const int mt = b * 32 + blockIdx.x * 2;
        uint32_t* d0 = g_OcT + ((size_t)mt * 8 + h) * 4096;
        uint32_t* d1 = g_OcT + ((size_t)(mt + 1) * 8 + h) * 4096;
        const uint4* s4 = (const uint4*)(smw + APS);
        for (int i = tid; i < 1024; i += 256) {
            ((uint4*)d0)[i] = s4[i];
            ((uint4*)d1)[i] = s4[1024 + i];
        }
    }
}

// ---------------------------------------------------------------------------
extern "C" void kernel_launch(void* const* d_in, const int* in_sizes, int n_in,
                              void* d_out, int out_size)
{
    const float* Q  = (const float*)d_in[0];
    const float* K  = (const float*)d_in[1];
    const float* V  = (const float*)d_in[2];
    const float* WQ = (const float*)d_in[3];
    const float* WK = (const float*)d_in[4];
    const float* WV = (const float*)d_in[5];
    const float* WO = (const float*)d_in[6];
    float* out = (float*)d_out;

    const size_t smemP = (size_t)PJ_WORDS * 4;     // 192 KB
    const size_t smemO = (size_t)OG_WORDS * 4;     // 160 KB
    const size_t smemA = (size_t)ASMEM_WORDS * 4;  // 128 KB
    cudaFuncSetAttribute(proj_mma_kernel, cudaFuncAttributeMaxDynamicSharedMemorySize, (int)smemP);
    cudaFuncSetAttribute(out_mma_kernel,  cudaFuncAttributeMaxDynamicSharedMemorySize, (int)smemO);
    cudaFuncSetAttribute(attn_mma_kernel, cudaFuncAttributeMaxDynamicSharedMemorySize, (int)smemA);

    prep_w_kernel<<<dim3(8, 8, 4), 128>>>(WQ, WK, WV, WO);

    proj_mma_kernel<<<dim3(H_, (B_ * S_) / 256, 3), 256, smemP>>>(Q, K, V);

    attn_mma_kernel<<<dim3(S_ / 128, H_, B_), 256, smemA>>>();

    out_mma_kernel<<<dim3(8, (B_ * S_) / 256), 256, smemO>>>(out);
}

// round 12
// speedup vs baseline: 1.0548x; 1.0548x over previous
#include <cuda_runtime.h>
#include <cstdint>

#define B_   4
#define S_   2048
#define D_   512
#define H_   8
#define DK_  64

// ---------------------------------------------------------------------------
// Scratch (allocation-free: __device__ globals)
// ---------------------------------------------------------------------------
__device__ uint32_t g_Qhi[B_*H_*S_*DK_];   // [(b*H+h)*32 + stile][4096]
__device__ uint32_t g_Qlo[B_*H_*S_*DK_];
__device__ uint32_t g_Khi[B_*H_*S_*DK_];
__device__ uint32_t g_Klo[B_*H_*S_*DK_];
__device__ uint32_t g_Vt [B_*H_*S_*DK_];   // transposed (rows = dk, k = s)
__device__ uint32_t g_OcT[B_*S_*D_];       // attn out kfmt: [mtile(128)*8 + kchunk][4096]
__device__ uint32_t g_Whi[3*8*8*4096];     // [(which*8+h)*8 + c][4096]
__device__ uint32_t g_Wlo[3*8*8*4096];
__device__ uint32_t g_WOt[8*8*4096];       // [c*8 + ntile][4096]

// ===========================================================================
// mma.sync tf32 helpers (baseline PTX, works on compute_103 target)
// ===========================================================================
__device__ __forceinline__ uint32_t f2tf32(float x) {
    uint32_t r; asm("cvt.rna.tf32.f32 %0, %1;" : "=r"(r) : "f"(x)); return r;
}
__device__ __forceinline__ void mma8(float* d,
                                     uint32_t a0, uint32_t a1, uint32_t a2, uint32_t a3,
                                     uint32_t b0, uint32_t b1) {
    asm volatile("mma.sync.aligned.m16n8k8.row.col.f32.tf32.tf32.f32 "
                 "{%0,%1,%2,%3}, {%4,%5,%6,%7}, {%8,%9}, {%0,%1,%2,%3};"
                 : "+f"(d[0]), "+f"(d[1]), "+f"(d[2]), "+f"(d[3])
                 : "r"(a0), "r"(a1), "r"(a2), "r"(a3), "r"(b0), "r"(b1));
}
__device__ __forceinline__ void cp16(uint32_t saddr, const void* g) {
    asm volatile("cp.async.cg.shared.global [%0], [%1], 16;" :: "r"(saddr), "l"(g) : "memory");
}
#define CP_COMMIT() asm volatile("cp.async.commit_group;" ::: "memory")
__device__ __forceinline__ uint32_t smem_u32(const void* p) {
    uint32_t a;
    asm("{ .reg .u64 t; cvta.to.shared.u64 t, %1; cvt.u32.u64 %0, t; }" : "=r"(a) : "l"(p));
    return a;
}

// kfmt, per 64x64 tile: word(row,k) = (ks*64+row)*8 + pos(kin)^sw,
//   ks=k>>3, kin=k&7, pos(kin) = (kin&3)*2 + (kin>>2),
//   sw = 4*(((row>>2)^(ks>>2))&1). Fragment (kin=t,t+4) = LDS.64 at 2t^sw.

// ---------------------------------------------------------------------------
// Loaders
// ---------------------------------------------------------------------------
__device__ __forceinline__ void ldg_rows(const float* __restrict__ src, int tid,
                                         int stride, float4 xa[4], float4 xb[4])
{
    const int r = tid >> 1, kh = tid & 1;
    #pragma unroll
    for (int j = 0; j < 4; j++) {
        const int ks = kh * 4 + j;
        xa[j] = *(const float4*)(src + (size_t)r * stride + ks * 8);
        xb[j] = *(const float4*)(src + (size_t)r * stride + ks * 8 + 4);
    }
}
__device__ __forceinline__ void sts_split(const float4 xa[4], const float4 xb[4],
                                          uint32_t* __restrict__ smw,
                                          int whi, int wlo, int tid)
{
    const int r = tid >> 1, kh = tid & 1;
    #pragma unroll
    for (int j = 0; j < 4; j++) {
        const int ks = kh * 4 + j;
        float x[8] = {xa[j].x, xa[j].y, xa[j].z, xa[j].w,
                      xb[j].x, xb[j].y, xb[j].z, xb[j].w};
        uint32_t h[8], l[8];
        #pragma unroll
        for (int e = 0; e < 8; e++) {
            h[e] = __float_as_uint(x[e]) & 0xFFFFE000u;
            l[e] = f2tf32(x[e] - __uint_as_float(h[e]));
        }
        const int sw = 4 * (((r >> 2) ^ (ks >> 2)) & 1);
        const uint32_t base = (uint32_t)((ks * 64 + r) * 8);
        *(uint4*)(smw + whi + base + (0 ^ sw)) = make_uint4(h[0], h[4], h[1], h[5]);
        *(uint4*)(smw + whi + base + (4 ^ sw)) = make_uint4(h[2], h[6], h[3], h[7]);
        *(uint4*)(smw + wlo + base + (0 ^ sw)) = make_uint4(l[0], l[4], l[1], l[5]);
        *(uint4*)(smw + wlo + base + (4 ^ sw)) = make_uint4(l[2], l[6], l[3], l[7]);
    }
}
__device__ __forceinline__ void ldg_T(const float* __restrict__ bsrc, int ldb,
                                      int tid, float wst[4][8])
{
    const int n = tid & 63, kh = tid >> 6;
    #pragma unroll
    for (int j = 0; j < 4; j++) {
        const int ks = kh * 4 + j;
        #pragma unroll
        for (int si = 0; si < 8; si++)
            wst[j][si] = bsrc[(size_t)(ks * 8 + si) * ldb + n];
    }
}
__device__ __forceinline__ void sts_T_split(const float wst[4][8],
                                            uint32_t* __restrict__ smw,
                                            int whi, int wlo, int tid)
{
    const int n = tid & 63, kh = tid >> 6;
    #pragma unroll
    for (int j = 0; j < 4; j++) {
        const int ks = kh * 4 + j;
        uint32_t h[8], l[8];
        #pragma unroll
        for (int e = 0; e < 8; e++) {
            h[e] = __float_as_uint(wst[j][e]) & 0xFFFFE000u;
            l[e] = f2tf32(wst[j][e] - __uint_as_float(h[e]));
        }
        const int sw = 4 * (((n >> 2) ^ (ks >> 2)) & 1);
        const uint32_t base = (uint32_t)((ks * 64 + n) * 8);
        *(uint4*)(smw + whi + base + (0 ^ sw)) = make_uint4(h[0], h[4], h[1], h[5]);
        *(uint4*)(smw + whi + base + (4 ^ sw)) = make_uint4(h[2], h[6], h[3], h[7]);
        *(uint4*)(smw + wlo + base + (0 ^ sw)) = make_uint4(l[0], l[4], l[1], l[5]);
        *(uint4*)(smw + wlo + base + (4 ^ sw)) = make_uint4(l[2], l[6], l[3], l[7]);
    }
}
__device__ __forceinline__ void sts_T_single(const float wst[4][8],
                                             uint32_t* __restrict__ smw,
                                             int whi, int tid)
{
    const int n = tid & 63, kh = tid >> 6;
    #pragma unroll
    for (int j = 0; j < 4; j++) {
        const int ks = kh * 4 + j;
        uint32_t h[8];
        #pragma unroll
        for (int e = 0; e < 8; e++) h[e] = f2tf32(wst[j][e]);
        const int sw = 4 * (((n >> 2) ^ (ks >> 2)) & 1);
        const uint32_t base = (uint32_t)((ks * 64 + n) * 8);
        *(uint4*)(smw + whi + base + (0 ^ sw)) = make_uint4(h[0], h[4], h[1], h[5]);
        *(uint4*)(smw + whi + base + (4 ^ sw)) = make_uint4(h[2], h[6], h[3], h[7]);
    }
}

// One 64x64x64 MMA chunk (m16 per warp rows row0/row0+8).
__device__ __forceinline__ void mma_chunk(const uint32_t* __restrict__ smw,
                                          int wAhi, int wAlo, int wBhi, int wBlo,
                                          int row0, int g, int offA, bool split,
                                          float acc[8][4])
{
    #pragma unroll
    for (int ks = 0; ks < 8; ks++) {
        const int off = offA ^ (4 * ((ks >> 2) & 1));
        uint2 ah0 = *(const uint2*)(smw + wAhi + (ks * 64 + row0) * 8 + off);
        uint2 ah1 = *(const uint2*)(smw + wAhi + (ks * 64 + row0 + 8) * 8 + off);
        uint2 al0, al1;
        if (split) {
            al0 = *(const uint2*)(smw + wAlo + (ks * 64 + row0) * 8 + off);
            al1 = *(const uint2*)(smw + wAlo + (ks * 64 + row0 + 8) * 8 + off);
        }
        #pragma unroll
        for (int nt = 0; nt < 8; nt++) {
            const uint32_t ba = (uint32_t)((ks * 64 + nt * 8 + g) * 8 + off);
            uint2 bh = *(const uint2*)(smw + wBhi + ba);
            mma8(acc[nt], ah0.x, ah1.x, ah0.y, ah1.y, bh.x, bh.y);
            if (split) {
                uint2 bl = *(const uint2*)(smw + wBlo + ba);
                mma8(acc[nt], al0.x, al1.x, al0.y, al1.y, bh.x, bh.y);
                mma8(acc[nt], ah0.x, ah1.x, ah0.y, ah1.y, bl.x, bl.y);
            }
        }
    }
}

// ===========================================================================
// prep_w: preformat weights into kfmt. grid (8, 8, 4), 128 thr.
// ===========================================================================
__global__ __launch_bounds__(128) void prep_w_kernel(const float* __restrict__ WQ,
                                                     const float* __restrict__ WK,
                                                     const float* __restrict__ WV,
                                                     const float* __restrict__ WO)
{
    __shared__ uint32_t smw[8192];
    const int tid = threadIdx.x;
    const int c  = blockIdx.x;
    const int hn = blockIdx.y;
    const int which = blockIdx.z;
    float wst[4][8];
    if (which < 3) {
        const float* W = (which == 0) ? WQ : (which == 1) ? WK : WV;
        const float* src = W + (size_t)hn * (D_ * DK_) + (size_t)c * 64 * DK_;
        ldg_T(src, DK_, tid, wst);
        sts_T_split(wst, smw, 0, 4096, tid);
        __syncthreads();
        uint32_t* dH = g_Whi + ((size_t)(which * 8 + hn) * 8 + c) * 4096;
        uint32_t* dL = g_Wlo + ((size_t)(which * 8 + hn) * 8 + c) * 4096;
        for (int i = tid; i < 1024; i += 128) {
            ((uint4*)dH)[i] = ((const uint4*)smw)[i];
            ((uint4*)dL)[i] = ((const uint4*)smw)[1024 + i];
        }
    } else {
        const float* src = WO + (size_t)c * 64 * D_ + hn * 64;
        ldg_T(src, D_, tid, wst);
        sts_T_single(wst, smw, 0, tid);
        __syncthreads();
        uint32_t* dW = g_WOt + ((size_t)(c * 8 + hn)) * 4096;
        for (int i = tid; i < 1024; i += 128)
            ((uint4*)dW)[i] = ((const uint4*)smw)[i];
    }
}

// ===========================================================================
// Projection GEMM: m-tile 64, 128 thr / 4 warps, m16/warp, split for all 3.
// A converted in-kernel (reg-staged); B streamed preformatted via cp.async.
// smem words: Ahi [0,4096) | Alo [4096,8192) | B0 hi/lo [8192,16384) |
//             B1 hi/lo [16384,24576).  Total 96 KB -> 2 CTA/SM.
// ===========================================================================
#define PR_B0  8192
#define PR_BSZ 8192
#define PR_WORDS 24576   // 96 KB

__global__ void __launch_bounds__(128, 2) proj_mma_kernel(const float* __restrict__ Qx,
                                                          const float* __restrict__ Kx,
                                                          const float* __restrict__ Vx)
{
    extern __shared__ uint32_t smw[];
    const uint32_t sbase = smem_u32(smw);

    const int which = blockIdx.z;
    const float* __restrict__ X = (which == 0) ? Qx : (which == 1) ? Kx : Vx;

    const int tid  = threadIdx.x;
    const int lane = tid & 31;
    const int w    = tid >> 5;
    const int g    = lane >> 2;
    const int t    = lane & 3;
    const int g2   = (g >> 2) & 1;
    const int row0 = w * 16 + g;
    const int offA = 2 * t ^ (4 * g2);
    const int pe = ((2 * t) & 3) * 2 + (t >> 1);
    const int po = ((2 * t + 1) & 3) * 2 + ((2 * t + 1) >> 2);

    const int h  = blockIdx.x;
    const int m0 = blockIdx.y * 64;
    const float* __restrict__ Xm = X + (size_t)m0 * D_;
    const uint32_t* __restrict__ Bh = g_Whi + (size_t)(which * 8 + h) * 8 * 4096;
    const uint32_t* __restrict__ Bl = g_Wlo + (size_t)(which * 8 + h) * 8 * 4096;

    float acc[8][4];
    #pragma unroll
    for (int nt = 0; nt < 8; nt++)
        #pragma unroll
        for (int j = 0; j < 4; j++) acc[nt][j] = 0.f;

    // stage A chunk 0 in regs
    float4 xa[4], xb[4];
    ldg_rows(Xm, tid, D_, xa, xb);

    // prologue: B chunk 0 -> buf 0
    {
        const uint4* sh = (const uint4*)(Bh);
        const uint4* sl = (const uint4*)(Bl);
        const uint32_t db = sbase + PR_B0 * 4;
        #pragma unroll
        for (int i = 0; i < 8; i++) {
            const int idx = tid + i * 128;
            cp16(db + idx * 16,            sh + idx);
            cp16(db + 4096 * 4 + idx * 16, sl + idx);
        }
        CP_COMMIT();
    }

    for (int c = 0; c < 8; c++) {
        const int bb = c & 1;

        sts_split(xa, xb, smw, 0, 4096, tid);   // A chunk c -> smem

        if (c < 7) {
            ldg_rows(Xm + (c + 1) * 64, tid, D_, xa, xb);   // stage A c+1
            const uint4* sh = (const uint4*)(Bh + (size_t)(c + 1) * 4096);
            const uint4* sl = (const uint4*)(Bl + (size_t)(c + 1) * 4096);
            const uint32_t db = sbase + (PR_B0 + (bb ^ 1) * PR_BSZ) * 4;
            #pragma unroll
            for (int i = 0; i < 8; i++) {
                const int idx = tid + i * 128;
                cp16(db + idx * 16,            sh + idx);
                cp16(db + 4096 * 4 + idx * 16, sl + idx);
            }
            CP_COMMIT();
            asm volatile("cp.async.wait_group 1;" ::: "memory");
        } else {
            asm volatile("cp.async.wait_group 0;" ::: "memory");
        }
        __syncthreads();

        const int bw = PR_B0 + bb * PR_BSZ;
        mma_chunk(smw, 0, 4096, bw, bw + 4096, row0, g, offA, true, acc);
        __syncthreads();
    }

    const int bb2 = m0 >> 11;
    const int st0 = (m0 & 2047) >> 6;
    const size_t tbase = ((size_t)((bb2 * H_ + h) * 32 + st0)) * 4096;

    if (which != 2) {
        // --- Q/K epilogue: split kfmt staged in smem, then linear copy ---
        #pragma unroll
        for (int j = 0; j < 2; j++) {
            const int r = row0 + 8 * j;
            #pragma unroll
            for (int nt = 0; nt < 8; nt++) {
                float p0 = acc[nt][2 * j], p1 = acc[nt][2 * j + 1];
                uint32_t h0 = __float_as_uint(p0) & 0xFFFFE000u;
                uint32_t h1 = __float_as_uint(p1) & 0xFFFFE000u;
                uint32_t l0 = f2tf32(p0 - __uint_as_float(h0));
                uint32_t l1 = f2tf32(p1 - __uint_as_float(h1));
                const int sw = 4 * ((((r >> 2) ^ (nt >> 2)) & 1));
                const uint32_t base = (uint32_t)((nt * 64 + r) * 8);
                smw[base + (pe ^ sw)] = h0;
                smw[base + (po ^ sw)] = h1;
                smw[4096 + base + (pe ^ sw)] = l0;
                smw[4096 + base + (po ^ sw)] = l1;
            }
        }
        __syncthreads();
        uint32_t* dH = (which == 0 ? g_Qhi : g_Khi) + tbase;
        uint32_t* dL = (which == 0 ? g_Qlo : g_Klo) + tbase;
        const uint4* s4 = (const uint4*)smw;
        for (int i = tid; i < 1024; i += 128) {
            ((uint4*)dH)[i] = s4[i];
            ((uint4*)dL)[i] = s4[1024 + i];
        }
    } else {
        // --- V epilogue: raw tf32 stage -> transpose -> kfmt Vt ---
        #pragma unroll
        for (int j = 0; j < 2; j++) {
            const int r = row0 + 8 * j;
            #pragma unroll
            for (int nt = 0; nt < 8; nt++) {
                smw[r * 64 + nt * 8 + 2 * t]     = f2tf32(acc[nt][2 * j]);
                smw[r * 64 + nt * 8 + 2 * t + 1] = f2tf32(acc[nt][2 * j + 1]);
            }
        }
        __syncthreads();
        {
            const int vdk = tid & 63, vsh = tid >> 6;
            #pragma unroll
            for (int j = 0; j < 4; j++) {
                const int sc = vsh * 4 + j;
                uint32_t v[8];
                #pragma unroll
                for (int si = 0; si < 8; si++)
                    v[si] = smw[(sc * 8 + si) * 64 + vdk];
                const int sw = 4 * (((vdk >> 2) ^ (sc >> 2)) & 1);
                const uint32_t base = (uint32_t)((sc * 64 + vdk) * 8);
                *(uint4*)(smw + 4096 + base + (0 ^ sw)) = make_uint4(v[0], v[4], v[1], v[5]);
                *(uint4*)(smw + 4096 + base + (4 ^ sw)) = make_uint4(v[2], v[6], v[3], v[7]);
            }
        }
        __syncthreads();
        uint32_t* dV = g_Vt + tbase;
        const uint4* s4 = (const uint4*)(smw + 4096);
        for (int i = tid; i < 1024; i += 128)
            ((uint4*)dV)[i] = s4[i];
    }
}

// ===========================================================================
// Output GEMM: fully preformatted streaming. m-tile 256, 256 thr, m32/warp.
// smem words: A0 [0,16384) | A1 [16384,32768) | B0 [32768,36864) | B1 [36864,40960)
// ===========================================================================
#define OG_B0 32768
#define OG_WORDS 40960   // 160 KB

__global__ void __launch_bounds__(256, 1) out_mma_kernel(float* __restrict__ out)
{
    extern __shared__ uint32_t smw[];
    const uint32_t sbase = smem_u32(smw);

    const int tid  = threadIdx.x;
    const int lane = tid & 31;
    const int w    = tid >> 5;
    const int g    = lane >> 2;
    const int t    = lane & 3;
    const int g2   = (g >> 2) & 1;
    const int ts   = w >> 1;
    const int rA0  = (w & 1) * 32 + g;

    const int n0t = blockIdx.x;
    const int mt0 = blockIdx.y * 4;

    float acc[2][8][4];
    #pragma unroll
    for (int mg = 0; mg < 2; mg++)
        #pragma unroll
        for (int nt = 0; nt < 8; nt++)
            #pragma unroll
            for (int j = 0; j < 4; j++) acc[mg][nt][j] = 0.f;

    {
        #pragma unroll
        for (int s = 0; s < 4; s++) {
            const uint4* sa = (const uint4*)(g_OcT + ((size_t)(mt0 + s) * 8 + 0) * 4096);
            const uint32_t da = sbase + (s * 4096) * 4;
            #pragma unroll
            for (int i = 0; i < 4; i++) {
                const int idx = tid + i * 256;
                cp16(da + idx * 16, sa + idx);
            }
        }
        const uint4* sb = (const uint4*)(g_WOt + ((size_t)(0 * 8 + n0t)) * 4096);
        const uint32_t db = sbase + OG_B0 * 4;
        #pragma unroll
        for (int i = 0; i < 4; i++) {
            const int idx = tid + i * 256;
            cp16(db + idx * 16, sb + idx);
        }
        CP_COMMIT();
    }

    for (int c = 0; c < 8; c++) {
        const int bb = c & 1;
        if (c < 7) {
            #pragma unroll
            for (int s = 0; s < 4; s++) {
                const uint4* sa = (const uint4*)(g_OcT + ((size_t)(mt0 + s) * 8 + (c + 1)) * 4096);
                const uint32_t da = sbase + ((bb ^ 1) * 16384 + s * 4096) * 4;
                #pragma unroll
                for (int i = 0; i < 4; i++) {
                    const int idx = tid + i * 256;
                    cp16(da + idx * 16, sa + idx);
                }
            }
            const uint4* sb = (const uint4*)(g_WOt + ((size_t)((c + 1) * 8 + n0t)) * 4096);
            const uint32_t db = sbase + (OG_B0 + (bb ^ 1) * 4096) * 4;
            #pragma unroll
            for (int i = 0; i < 4; i++) {
                const int idx = tid + i * 256;
                cp16(db + idx * 16, sb + idx);
            }
            CP_COMMIT();
            asm volatile("cp.async.wait_group 1;" ::: "memory");
        } else {
            asm volatile("cp.async.wait_group 0;" ::: "memory");
        }
        __syncthreads();

        const uint32_t aw = bb * 16384 + ts * 4096;
        const uint32_t bw = OG_B0 + bb * 4096;
        #pragma unroll
        for (int ks = 0; ks < 8; ks++) {
            const int off = 2 * t ^ (4 * (g2 ^ ((ks >> 2) & 1)));
            uint2 a[4];
            #pragma unroll
            for (int q = 0; q < 4; q++)
                a[q] = *(const uint2*)(smw + aw + (ks * 64 + rA0 + 8 * q) * 8 + off);
            #pragma unroll
            for (int nt = 0; nt < 8; nt++) {
                uint2 bv = *(const uint2*)(smw + bw + (ks * 64 + nt * 8 + g) * 8 + off);
                mma8(acc[0][nt], a[0].x, a[1].x, a[0].y, a[1].y, bv.x, bv.y);
                mma8(acc[1][nt], a[2].x, a[3].x, a[2].y, a[3].y, bv.x, bv.y);
            }
        }
        __syncthreads();
    }

    const int m0 = mt0 * 64;
    #pragma unroll
    for (int mg = 0; mg < 2; mg++)
        #pragma unroll
        for (int j = 0; j < 2; j++) {
            const int m = m0 + ts * 64 + rA0 + 16 * mg + 8 * j;
            float* dst = out + (size_t)m * D_ + n0t * 64;
            #pragma unroll
            for (int nt = 0; nt < 8; nt++)
                *(float2*)(dst + nt * 8 + t * 2) =
                    make_float2(acc[mg][nt][2 * j], acc[mg][nt][2 * j + 1]);
        }
}

// ===========================================================================
// Flash attention: CTA = (b, h, 128 q-rows), 256 thr.
// smem words: buf0 [KHI 0 | KLO 4096 | VT 8192], buf1 +12288, PS 24576 (2 tiles)
// ===========================================================================
#define ABUF 12288
#define APS  24576
#define ASMEM_WORDS 32768   // 128 KB

__global__ void __launch_bounds__(256, 1) attn_mma_kernel()
{
    extern __shared__ uint32_t smw[];
    const uint32_t sbase = smem_u32(smw);

    const int tid  = threadIdx.x;
    const int lane = tid & 31;
    const int w    = tid >> 5;
    const int g    = lane >> 2;
    const int t    = lane & 3;
    const int g2   = (g >> 2) & 1;
    const int row0 = w * 16 + g;
    const int offA = 2 * t ^ (4 * g2);
    const int pe = ((2 * t) & 3) * 2 + (t >> 1);
    const int po = ((2 * t + 1) & 3) * 2 + ((2 * t + 1) >> 2);

    const int h  = blockIdx.y;
    const int b  = blockIdx.z;
    const size_t kvbase = ((size_t)(b * H_ + h)) * 32 * 4096;

    {
        const uint4* sK = (const uint4*)(g_Khi + kvbase);
        const uint4* sL = (const uint4*)(g_Klo + kvbase);
        const uint4* sV = (const uint4*)(g_Vt  + kvbase);
        #pragma unroll
        for (int k = 0; k < 4; k++) {
            const int i = tid + k * 256;
            cp16(sbase + i * 16,          sK + i);
            cp16(sbase + 16384 + i * 16,  sL + i);
            cp16(sbase + 32768 + i * 16,  sV + i);
        }
        CP_COMMIT();
    }

    uint2 qh0[8], qh1[8], ql0[8], ql1[8];
    {
        const int qst = blockIdx.x * 2 + (row0 >> 6);
        const size_t qtb = ((size_t)(b * H_ + h) * 32 + qst) * 4096;
        const int r = row0 & 63;
        #pragma unroll
        for (int ks = 0; ks < 8; ks++) {
            const int off = offA ^ (4 * ((ks >> 2) & 1));
            const size_t i0 = qtb + (ks * 64 + r) * 8 + off;
            const size_t i1 = qtb + (ks * 64 + r + 8) * 8 + off;
            qh0[ks] = *(const uint2*)(g_Qhi + i0);
            qh1[ks] = *(const uint2*)(g_Qhi + i1);
            ql0[ks] = *(const uint2*)(g_Qlo + i0);
            ql1[ks] = *(const uint2*)(g_Qlo + i1);
        }
    }

    float o[8][4];
    #pragma unroll
    for (int nt = 0; nt < 8; nt++)
        #pragma unroll
        for (int j = 0; j < 4; j++) o[nt][j] = 0.f;
    float mrun[2] = {-1e30f, -1e30f}, lrun[2] = {0.f, 0.f};
    const float Cc = 0.125f * 1.4426950408889634f;

    const int ptile = APS + (row0 >> 6) * 4096;
    const int pr    = row0 & 63;

    for (int it = 0; it < 32; it++) {
        const int cur = it & 1;

        if (it < 31) {
            const uint32_t db = sbase + (cur ^ 1) * (ABUF * 4);
            const size_t tb = kvbase + (size_t)(it + 1) * 4096;
            const uint4* sK = (const uint4*)(g_Khi + tb);
            const uint4* sL = (const uint4*)(g_Klo + tb);
            const uint4* sV = (const uint4*)(g_Vt  + tb);
            #pragma unroll
            for (int k = 0; k < 4; k++) {
                const int i = tid + k * 256;
                cp16(db + i * 16,          sK + i);
                cp16(db + 16384 + i * 16,  sL + i);
                cp16(db + 32768 + i * 16,  sV + i);
            }
            CP_COMMIT();
            asm volatile("cp.async.wait_group 1;" ::: "memory");
        } else {
            asm volatile("cp.async.wait_group 0;" ::: "memory");
        }
        __syncthreads();

        const int bk = cur * ABUF;

        float accS[8][4];
        #pragma unroll
        for (int nt = 0; nt < 8; nt++)
            #pragma unroll
            for (int j = 0; j < 4; j++) accS[nt][j] = 0.f;

        #pragma unroll
        for (int ks = 0; ks < 8; ks++) {
            const int off = offA ^ (4 * ((ks >> 2) & 1));
            #pragma unroll
            for (int nt = 0; nt < 8; nt++) {
                const uint32_t ba = (uint32_t)(bk + (ks * 64 + nt * 8 + g) * 8 + off);
                uint2 bh = *(const uint2*)(smw + ba);
                uint2 bl = *(const uint2*)(smw + 4096 + ba);
                mma8(accS[nt], qh0[ks].x, qh1[ks].x, qh0[ks].y, qh1[ks].y, bh.x, bh.y);
                mma8(accS[nt], ql0[ks].x, ql1[ks].x, ql0[ks].y, ql1[ks].y, bh.x, bh.y);
                mma8(accS[nt], qh0[ks].x, qh1[ks].x, qh0[ks].y, qh1[ks].y, bl.x, bl.y);
            }
        }

        #pragma unroll
        for (int j = 0; j < 2; j++) {
            float m = -1e30f;
            #pragma unroll
            for (int nt = 0; nt < 8; nt++)
                m = fmaxf(m, fmaxf(accS[nt][2 * j], accS[nt][2 * j + 1]));
            m = fmaxf(m, __shfl_xor_sync(0xffffffffu, m, 1));
            m = fmaxf(m, __shfl_xor_sync(0xffffffffu, m, 2));

            float mnew = fmaxf(mrun[j], m);
            float scl  = exp2f((mrun[j] - mnew) * Cc);
            mrun[j] = mnew;

            const int prow = pr + 8 * j;
            float sum = 0.f;
            #pragma unroll
            for (int nt = 0; nt < 8; nt++) {
                float p0 = exp2f((accS[nt][2 * j]     - mnew) * Cc);
                float p1 = exp2f((accS[nt][2 * j + 1] - mnew) * Cc);
                sum += p0 + p1;
                const int sw = 4 * ((g2 ^ (nt >> 2)) & 1);
                const uint32_t base = (uint32_t)(ptile + (nt * 64 + prow) * 8);
                smw[base + (pe ^ sw)] = f2tf32(p0);
                smw[base + (po ^ sw)] = f2tf32(p1);
                o[nt][2 * j]     *= scl;
                o[nt][2 * j + 1] *= scl;
            }
            sum += __shfl_xor_sync(0xffffffffu, sum, 1);
            sum += __shfl_xor_sync(0xffffffffu, sum, 2);
            lrun[j] = lrun[j] * scl + sum;
        }
        __syncwarp();

        #pragma unroll
        for (int ks = 0; ks < 8; ks++) {
            const int off = offA ^ (4 * ((ks >> 2) & 1));
            uint2 p0 = *(const uint2*)(smw + ptile + (ks * 64 + pr) * 8 + off);
            uint2 p1 = *(const uint2*)(smw + ptile + (ks * 64 + pr + 8) * 8 + off);
            #pragma unroll
            for (int nt = 0; nt < 8; nt++) {
                uint2 bv = *(const uint2*)(smw + bk + 8192 + (ks * 64 + nt * 8 + g) * 8 + off);
                mma8(o[nt], p0.x, p1.x, p0.y, p1.y, bv.x, bv.y);
            }
        }
        __syncthreads();
    }

    // --- Epilogue: normalize, write kfmt tf32 tiles into g_OcT ---
    {
        const int stl = row0 >> 6;
        const int rr0 = row0 & 63;
        #pragma unroll
        for (int j = 0; j < 2; j++) {
            const float inv = 1.f / lrun[j];
            const int rr = rr0 + 8 * j;
            #pragma unroll
            for (int nt = 0; nt < 8; nt++) {
                const int sw = 4 * (g2 ^ ((nt >> 2) & 1));
                const uint32_t base = (uint32_t)(APS + stl * 4096 + (nt * 64 + rr) * 8);
                smw[base + (pe ^ sw)] = f2tf32(o[nt][2 * j] * inv);
                smw[base + (po ^ sw)] = f2tf32(o[nt][2 * j + 1] * inv);
            }
        }
        __syncthreads();
        const int mt = b * 32 + blockIdx.x * 2;
        uint32_t* d0 = g_OcT + ((size_t)mt * 8 + h) * 4096;
        uint32_t* d1 = g_OcT + ((size_t)(mt + 1) * 8 + h) * 4096;
        const uint4* s4 = (const uint4*)(smw + APS);
        for (int i = tid; i < 1024; i += 256) {
            ((uint4*)d0)[i] = s4[i];
            ((uint4*)d1)[i] = s4[1024 + i];
        }
    }
}

// ---------------------------------------------------------------------------
extern "C" void kernel_launch(void* const* d_in, const int* in_sizes, int n_in,
                              void* d_out, int out_size)
{
    const float* Q  = (const float*)d_in[0];
    const float* K  = (const float*)d_in[1];
    const float* V  = (const float*)d_in[2];
    const float* WQ = (const float*)d_in[3];
    const float* WK = (const float*)d_in[4];
    const float* WV = (const float*)d_in[5];
    const float* WO = (const float*)d_in[6];
    float* out = (float*)d_out;

    const size_t smemP = (size_t)PR_WORDS * 4;     // 96 KB
    const size_t smemO = (size_t)OG_WORDS * 4;     // 160 KB
    const size_t smemA = (size_t)ASMEM_WORDS * 4;  // 128 KB
    cudaFuncSetAttribute(proj_mma_kernel, cudaFuncAttributeMaxDynamicSharedMemorySize, (int)smemP);
    cudaFuncSetAttribute(out_mma_kernel,  cudaFuncAttributeMaxDynamicSharedMemorySize, (int)smemO);
    cudaFuncSetAttribute(attn_mma_kernel, cudaFuncAttributeMaxDynamicSharedMemorySize, (int)smemA);

    prep_w_kernel<<<dim3(8, 8, 4), 128>>>(WQ, WK, WV, WO);

    proj_mma_kernel<<<dim3(H_, (B_ * S_) / 64, 3), 128, smemP>>>(Q, K, V);

    attn_mma_kernel<<<dim3(S_ / 128, H_, B_), 256, smemA>>>();

    out_mma_kernel<<<dim3(8, (B_ * S_) / 256), 256, smemO>>>(out);
}

// round 13
// speedup vs baseline: 1.1513x; 1.0915x over previous
#include <cuda_runtime.h>
#include <cstdint>

#define B_   4
#define S_   2048
#define D_   512
#define H_   8
#define DK_  64

// ---------------------------------------------------------------------------
// Scratch (allocation-free: __device__ globals)
// ---------------------------------------------------------------------------
__device__ uint32_t g_Qhi[B_*H_*S_*DK_];   // [(b*H+h)*32 + stile][4096]
__device__ uint32_t g_Qlo[B_*H_*S_*DK_];
__device__ uint32_t g_Khi[B_*H_*S_*DK_];
__device__ uint32_t g_Klo[B_*H_*S_*DK_];
__device__ uint32_t g_Vt [B_*H_*S_*DK_];   // transposed (rows = dk, k = s)
__device__ uint32_t g_OcT[B_*S_*D_];       // attn out kfmt: [mtile(64)*8 + kchunk][4096]
__device__ uint32_t g_Whi[3*8*8*4096];     // [(which*8+h)*8 + c][4096]
__device__ uint32_t g_Wlo[3*8*8*4096];
__device__ uint32_t g_WOt[8*8*4096];       // [c*8 + ntile][4096]

// ===========================================================================
// mma.sync tf32 helpers (baseline PTX, works on compute_103 target)
// ===========================================================================
__device__ __forceinline__ uint32_t f2tf32(float x) {
    uint32_t r; asm("cvt.rna.tf32.f32 %0, %1;" : "=r"(r) : "f"(x)); return r;
}
__device__ __forceinline__ void mma8(float* d,
                                     uint32_t a0, uint32_t a1, uint32_t a2, uint32_t a3,
                                     uint32_t b0, uint32_t b1) {
    asm volatile("mma.sync.aligned.m16n8k8.row.col.f32.tf32.tf32.f32 "
                 "{%0,%1,%2,%3}, {%4,%5,%6,%7}, {%8,%9}, {%0,%1,%2,%3};"
                 : "+f"(d[0]), "+f"(d[1]), "+f"(d[2]), "+f"(d[3])
                 : "r"(a0), "r"(a1), "r"(a2), "r"(a3), "r"(b0), "r"(b1));
}
__device__ __forceinline__ void cp16(uint32_t saddr, const void* g) {
    asm volatile("cp.async.cg.shared.global [%0], [%1], 16;" :: "r"(saddr), "l"(g) : "memory");
}
#define CP_COMMIT() asm volatile("cp.async.commit_group;" ::: "memory")
__device__ __forceinline__ uint32_t smem_u32(const void* p) {
    uint32_t a;
    asm("{ .reg .u64 t; cvta.to.shared.u64 t, %1; cvt.u32.u64 %0, t; }" : "=r"(a) : "l"(p));
    return a;
}

// kfmt, per 64x64 tile: word(row,k) = (ks*64+row)*8 + pos(kin)^sw,
//   ks=k>>3, kin=k&7, pos(kin) = (kin&3)*2 + (kin>>2),
//   sw = 4*(((row>>2)^(ks>>2))&1). Fragment (kin=t,t+4) = LDS.64 at 2t^sw.

// ---------------------------------------------------------------------------
// Loaders
// ---------------------------------------------------------------------------
__device__ __forceinline__ void ldg_rows(const float* __restrict__ src, int tid,
                                         int stride, float4 xa[4], float4 xb[4])
{
    const int r = tid >> 1, kh = tid & 1;
    #pragma unroll
    for (int j = 0; j < 4; j++) {
        const int ks = kh * 4 + j;
        xa[j] = *(const float4*)(src + (size_t)r * stride + ks * 8);
        xb[j] = *(const float4*)(src + (size_t)r * stride + ks * 8 + 4);
    }
}
__device__ __forceinline__ void sts_split(const float4 xa[4], const float4 xb[4],
                                          uint32_t* __restrict__ smw,
                                          int whi, int wlo, int tid)
{
    const int r = tid >> 1, kh = tid & 1;
    #pragma unroll
    for (int j = 0; j < 4; j++) {
        const int ks = kh * 4 + j;
        float x[8] = {xa[j].x, xa[j].y, xa[j].z, xa[j].w,
                      xb[j].x, xb[j].y, xb[j].z, xb[j].w};
        uint32_t h[8], l[8];
        #pragma unroll
        for (int e = 0; e < 8; e++) {
            h[e] = __float_as_uint(x[e]) & 0xFFFFE000u;
            l[e] = f2tf32(x[e] - __uint_as_float(h[e]));
        }
        const int sw = 4 * (((r >> 2) ^ (ks >> 2)) & 1);
        const uint32_t base = (uint32_t)((ks * 64 + r) * 8);
        *(uint4*)(smw + whi + base + (0 ^ sw)) = make_uint4(h[0], h[4], h[1], h[5]);
        *(uint4*)(smw + whi + base + (4 ^ sw)) = make_uint4(h[2], h[6], h[3], h[7]);
        *(uint4*)(smw + wlo + base + (0 ^ sw)) = make_uint4(l[0], l[4], l[1], l[5]);
        *(uint4*)(smw + wlo + base + (4 ^ sw)) = make_uint4(l[2], l[6], l[3], l[7]);
    }
}
__device__ __forceinline__ void ldg_T(const float* __restrict__ bsrc, int ldb,
                                      int tid, float wst[4][8])
{
    const int n = tid & 63, kh = tid >> 6;
    #pragma unroll
    for (int j = 0; j < 4; j++) {
        const int ks = kh * 4 + j;
        #pragma unroll
        for (int si = 0; si < 8; si++)
            wst[j][si] = bsrc[(size_t)(ks * 8 + si) * ldb + n];
    }
}
__device__ __forceinline__ void sts_T_split(const float wst[4][8],
                                            uint32_t* __restrict__ smw,
                                            int whi, int wlo, int tid)
{
    const int n = tid & 63, kh = tid >> 6;
    #pragma unroll
    for (int j = 0; j < 4; j++) {
        const int ks = kh * 4 + j;
        uint32_t h[8], l[8];
        #pragma unroll
        for (int e = 0; e < 8; e++) {
            h[e] = __float_as_uint(wst[j][e]) & 0xFFFFE000u;
            l[e] = f2tf32(wst[j][e] - __uint_as_float(h[e]));
        }
        const int sw = 4 * (((n >> 2) ^ (ks >> 2)) & 1);
        const uint32_t base = (uint32_t)((ks * 64 + n) * 8);
        *(uint4*)(smw + whi + base + (0 ^ sw)) = make_uint4(h[0], h[4], h[1], h[5]);
        *(uint4*)(smw + whi + base + (4 ^ sw)) = make_uint4(h[2], h[6], h[3], h[7]);
        *(uint4*)(smw + wlo + base + (0 ^ sw)) = make_uint4(l[0], l[4], l[1], l[5]);
        *(uint4*)(smw + wlo + base + (4 ^ sw)) = make_uint4(l[2], l[6], l[3], l[7]);
    }
}
__device__ __forceinline__ void sts_T_single(const float wst[4][8],
                                             uint32_t* __restrict__ smw,
                                             int whi, int tid)
{
    const int n = tid & 63, kh = tid >> 6;
    #pragma unroll
    for (int j = 0; j < 4; j++) {
        const int ks = kh * 4 + j;
        uint32_t h[8];
        #pragma unroll
        for (int e = 0; e < 8; e++) h[e] = f2tf32(wst[j][e]);
        const int sw = 4 * (((n >> 2) ^ (ks >> 2)) & 1);
        const uint32_t base = (uint32_t)((ks * 64 + n) * 8);
        *(uint4*)(smw + whi + base + (0 ^ sw)) = make_uint4(h[0], h[4], h[1], h[5]);
        *(uint4*)(smw + whi + base + (4 ^ sw)) = make_uint4(h[2], h[6], h[3], h[7]);
    }
}

// One 64x64x64 MMA chunk (m16 per warp rows row0/row0+8).
__device__ __forceinline__ void mma_chunk(const uint32_t* __restrict__ smw,
                                          int wAhi, int wAlo, int wBhi, int wBlo,
                                          int row0, int g, int offA, bool split,
                                          float acc[8][4])
{
    #pragma unroll
    for (int ks = 0; ks < 8; ks++) {
        const int off = offA ^ (4 * ((ks >> 2) & 1));
        uint2 ah0 = *(const uint2*)(smw + wAhi + (ks * 64 + row0) * 8 + off);
        uint2 ah1 = *(const uint2*)(smw + wAhi + (ks * 64 + row0 + 8) * 8 + off);
        uint2 al0, al1;
        if (split) {
            al0 = *(const uint2*)(smw + wAlo + (ks * 64 + row0) * 8 + off);
            al1 = *(const uint2*)(smw + wAlo + (ks * 64 + row0 + 8) * 8 + off);
        }
        #pragma unroll
        for (int nt = 0; nt < 8; nt++) {
            const uint32_t ba = (uint32_t)((ks * 64 + nt * 8 + g) * 8 + off);
            uint2 bh = *(const uint2*)(smw + wBhi + ba);
            mma8(acc[nt], ah0.x, ah1.x, ah0.y, ah1.y, bh.x, bh.y);
            if (split) {
                uint2 bl = *(const uint2*)(smw + wBlo + ba);
                mma8(acc[nt], al0.x, al1.x, al0.y, al1.y, bh.x, bh.y);
                mma8(acc[nt], ah0.x, ah1.x, ah0.y, ah1.y, bl.x, bl.y);
            }
        }
    }
}

// ===========================================================================
// prep_w: preformat weights into kfmt. grid (8, 8, 4), 128 thr.
// ===========================================================================
__global__ __launch_bounds__(128) void prep_w_kernel(const float* __restrict__ WQ,
                                                     const float* __restrict__ WK,
                                                     const float* __restrict__ WV,
                                                     const float* __restrict__ WO)
{
    __shared__ uint32_t smw[8192];
    const int tid = threadIdx.x;
    const int c  = blockIdx.x;
    const int hn = blockIdx.y;
    const int which = blockIdx.z;
    float wst[4][8];
    if (which < 3) {
        const float* W = (which == 0) ? WQ : (which == 1) ? WK : WV;
        const float* src = W + (size_t)hn * (D_ * DK_) + (size_t)c * 64 * DK_;
        ldg_T(src, DK_, tid, wst);
        sts_T_split(wst, smw, 0, 4096, tid);
        __syncthreads();
        uint32_t* dH = g_Whi + ((size_t)(which * 8 + hn) * 8 + c) * 4096;
        uint32_t* dL = g_Wlo + ((size_t)(which * 8 + hn) * 8 + c) * 4096;
        for (int i = tid; i < 1024; i += 128) {
            ((uint4*)dH)[i] = ((const uint4*)smw)[i];
            ((uint4*)dL)[i] = ((const uint4*)smw)[1024 + i];
        }
    } else {
        const float* src = WO + (size_t)c * 64 * D_ + hn * 64;
        ldg_T(src, D_, tid, wst);
        sts_T_single(wst, smw, 0, tid);
        __syncthreads();
        uint32_t* dW = g_WOt + ((size_t)(c * 8 + hn)) * 4096;
        for (int i = tid; i < 1024; i += 128)
            ((uint4*)dW)[i] = ((const uint4*)smw)[i];
    }
}

// ===========================================================================
// Projection GEMM: m-tile 64, 128 thr / 4 warps, m16/warp, split for all 3.
// A converted in-kernel (reg-staged); B streamed preformatted via cp.async.
// smem words: Ahi [0,4096) | Alo [4096,8192) | B0 hi/lo [8192,16384) |
//             B1 hi/lo [16384,24576).  Total 96 KB -> 2 CTA/SM.
// ===========================================================================
#define PR_B0  8192
#define PR_BSZ 8192
#define PR_WORDS 24576   // 96 KB

__global__ void __launch_bounds__(128, 2) proj_mma_kernel(const float* __restrict__ Qx,
                                                          const float* __restrict__ Kx,
                                                          const float* __restrict__ Vx)
{
    extern __shared__ uint32_t smw[];
    const uint32_t sbase = smem_u32(smw);

    const int which = blockIdx.z;
    const float* __restrict__ X = (which == 0) ? Qx : (which == 1) ? Kx : Vx;

    const int tid  = threadIdx.x;
    const int lane = tid & 31;
    const int w    = tid >> 5;
    const int g    = lane >> 2;
    const int t    = lane & 3;
    const int g2   = (g >> 2) & 1;
    const int row0 = w * 16 + g;
    const int offA = 2 * t ^ (4 * g2);
    const int pe = ((2 * t) & 3) * 2 + (t >> 1);
    const int po = ((2 * t + 1) & 3) * 2 + ((2 * t + 1) >> 2);

    const int h  = blockIdx.x;
    const int m0 = blockIdx.y * 64;
    const float* __restrict__ Xm = X + (size_t)m0 * D_;
    const uint32_t* __restrict__ Bh = g_Whi + (size_t)(which * 8 + h) * 8 * 4096;
    const uint32_t* __restrict__ Bl = g_Wlo + (size_t)(which * 8 + h) * 8 * 4096;

    float acc[8][4];
    #pragma unroll
    for (int nt = 0; nt < 8; nt++)
        #pragma unroll
        for (int j = 0; j < 4; j++) acc[nt][j] = 0.f;

    float4 xa[4], xb[4];
    ldg_rows(Xm, tid, D_, xa, xb);

    {
        const uint4* sh = (const uint4*)(Bh);
        const uint4* sl = (const uint4*)(Bl);
        const uint32_t db = sbase + PR_B0 * 4;
        #pragma unroll
        for (int i = 0; i < 8; i++) {
            const int idx = tid + i * 128;
            cp16(db + idx * 16,            sh + idx);
            cp16(db + 4096 * 4 + idx * 16, sl + idx);
        }
        CP_COMMIT();
    }

    for (int c = 0; c < 8; c++) {
        const int bb = c & 1;

        sts_split(xa, xb, smw, 0, 4096, tid);

        if (c < 7) {
            ldg_rows(Xm + (c + 1) * 64, tid, D_, xa, xb);
            const uint4* sh = (const uint4*)(Bh + (size_t)(c + 1) * 4096);
            const uint4* sl = (const uint4*)(Bl + (size_t)(c + 1) * 4096);
            const uint32_t db = sbase + (PR_B0 + (bb ^ 1) * PR_BSZ) * 4;
            #pragma unroll
            for (int i = 0; i < 8; i++) {
                const int idx = tid + i * 128;
                cp16(db + idx * 16,            sh + idx);
                cp16(db + 4096 * 4 + idx * 16, sl + idx);
            }
            CP_COMMIT();
            asm volatile("cp.async.wait_group 1;" ::: "memory");
        } else {
            asm volatile("cp.async.wait_group 0;" ::: "memory");
        }
        __syncthreads();

        const int bw = PR_B0 + bb * PR_BSZ;
        mma_chunk(smw, 0, 4096, bw, bw + 4096, row0, g, offA, true, acc);
        __syncthreads();
    }

    const int bb2 = m0 >> 11;
    const int st0 = (m0 & 2047) >> 6;
    const size_t tbase = ((size_t)((bb2 * H_ + h) * 32 + st0)) * 4096;

    if (which != 2) {
        #pragma unroll
        for (int j = 0; j < 2; j++) {
            const int r = row0 + 8 * j;
            #pragma unroll
            for (int nt = 0; nt < 8; nt++) {
                float p0 = acc[nt][2 * j], p1 = acc[nt][2 * j + 1];
                uint32_t h0 = __float_as_uint(p0) & 0xFFFFE000u;
                uint32_t h1 = __float_as_uint(p1) & 0xFFFFE000u;
                uint32_t l0 = f2tf32(p0 - __uint_as_float(h0));
                uint32_t l1 = f2tf32(p1 - __uint_as_float(h1));
                const int sw = 4 * ((((r >> 2) ^ (nt >> 2)) & 1));
                const uint32_t base = (uint32_t)((nt * 64 + r) * 8);
                smw[base + (pe ^ sw)] = h0;
                smw[base + (po ^ sw)] = h1;
                smw[4096 + base + (pe ^ sw)] = l0;
                smw[4096 + base + (po ^ sw)] = l1;
            }
        }
        __syncthreads();
        uint32_t* dH = (which == 0 ? g_Qhi : g_Khi) + tbase;
        uint32_t* dL = (which == 0 ? g_Qlo : g_Klo) + tbase;
        const uint4* s4 = (const uint4*)smw;
        for (int i = tid; i < 1024; i += 128) {
            ((uint4*)dH)[i] = s4[i];
            ((uint4*)dL)[i] = s4[1024 + i];
        }
    } else {
        #pragma unroll
        for (int j = 0; j < 2; j++) {
            const int r = row0 + 8 * j;
            #pragma unroll
            for (int nt = 0; nt < 8; nt++) {
                smw[r * 64 + nt * 8 + 2 * t]     = f2tf32(acc[nt][2 * j]);
                smw[r * 64 + nt * 8 + 2 * t + 1] = f2tf32(acc[nt][2 * j + 1]);
            }
        }
        __syncthreads();
        {
            const int vdk = tid & 63, vsh = tid >> 6;
            #pragma unroll
            for (int j = 0; j < 4; j++) {
                const int sc = vsh * 4 + j;
                uint32_t v[8];
                #pragma unroll
                for (int si = 0; si < 8; si++)
                    v[si] = smw[(sc * 8 + si) * 64 + vdk];
                const int sw = 4 * (((vdk >> 2) ^ (sc >> 2)) & 1);
                const uint32_t base = (uint32_t)((sc * 64 + vdk) * 8);
                *(uint4*)(smw + 4096 + base + (0 ^ sw)) = make_uint4(v[0], v[4], v[1], v[5]);
                *(uint4*)(smw + 4096 + base + (4 ^ sw)) = make_uint4(v[2], v[6], v[3], v[7]);
            }
        }
        __syncthreads();
        uint32_t* dV = g_Vt + tbase;
        const uint4* s4 = (const uint4*)(smw + 4096);
        for (int i = tid; i < 1024; i += 128)
            ((uint4*)dV)[i] = s4[i];
    }
}

// ===========================================================================
// Output GEMM: fully preformatted streaming. m-tile 256, 256 thr, m32/warp.
// smem words: A0 [0,16384) | A1 [16384,32768) | B0 [32768,36864) | B1 [36864,40960)
// ===========================================================================
#define OG_B0 32768
#define OG_WORDS 40960   // 160 KB

__global__ void __launch_bounds__(256, 1) out_mma_kernel(float* __restrict__ out)
{
    extern __shared__ uint32_t smw[];
    const uint32_t sbase = smem_u32(smw);

    const int tid  = threadIdx.x;
    const int lane = tid & 31;
    const int w    = tid >> 5;
    const int g    = lane >> 2;
    const int t    = lane & 3;
    const int g2   = (g >> 2) & 1;
    const int ts   = w >> 1;
    const int rA0  = (w & 1) * 32 + g;

    const int n0t = blockIdx.x;
    const int mt0 = blockIdx.y * 4;

    float acc[2][8][4];
    #pragma unroll
    for (int mg = 0; mg < 2; mg++)
        #pragma unroll
        for (int nt = 0; nt < 8; nt++)
            #pragma unroll
            for (int j = 0; j < 4; j++) acc[mg][nt][j] = 0.f;

    {
        #pragma unroll
        for (int s = 0; s < 4; s++) {
            const uint4* sa = (const uint4*)(g_OcT + ((size_t)(mt0 + s) * 8 + 0) * 4096);
            const uint32_t da = sbase + (s * 4096) * 4;
            #pragma unroll
            for (int i = 0; i < 4; i++) {
                const int idx = tid + i * 256;
                cp16(da + idx * 16, sa + idx);
            }
        }
        const uint4* sb = (const uint4*)(g_WOt + ((size_t)(0 * 8 + n0t)) * 4096);
        const uint32_t db = sbase + OG_B0 * 4;
        #pragma unroll
        for (int i = 0; i < 4; i++) {
            const int idx = tid + i * 256;
            cp16(db + idx * 16, sb + idx);
        }
        CP_COMMIT();
    }

    for (int c = 0; c < 8; c++) {
        const int bb = c & 1;
        if (c < 7) {
            #pragma unroll
            for (int s = 0; s < 4; s++) {
                const uint4* sa = (const uint4*)(g_OcT + ((size_t)(mt0 + s) * 8 + (c + 1)) * 4096);
                const uint32_t da = sbase + ((bb ^ 1) * 16384 + s * 4096) * 4;
                #pragma unroll
                for (int i = 0; i < 4; i++) {
                    const int idx = tid + i * 256;
                    cp16(da + idx * 16, sa + idx);
                }
            }
            const uint4* sb = (const uint4*)(g_WOt + ((size_t)((c + 1) * 8 + n0t)) * 4096);
            const uint32_t db = sbase + (OG_B0 + (bb ^ 1) * 4096) * 4;
            #pragma unroll
            for (int i = 0; i < 4; i++) {
                const int idx = tid + i * 256;
                cp16(db + idx * 16, sb + idx);
            }
            CP_COMMIT();
            asm volatile("cp.async.wait_group 1;" ::: "memory");
        } else {
            asm volatile("cp.async.wait_group 0;" ::: "memory");
        }
        __syncthreads();

        const uint32_t aw = bb * 16384 + ts * 4096;
        const uint32_t bw = OG_B0 + bb * 4096;
        #pragma unroll
        for (int ks = 0; ks < 8; ks++) {
            const int off = 2 * t ^ (4 * (g2 ^ ((ks >> 2) & 1)));
            uint2 a[4];
            #pragma unroll
            for (int q = 0; q < 4; q++)
                a[q] = *(const uint2*)(smw + aw + (ks * 64 + rA0 + 8 * q) * 8 + off);
            #pragma unroll
            for (int nt = 0; nt < 8; nt++) {
                uint2 bv = *(const uint2*)(smw + bw + (ks * 64 + nt * 8 + g) * 8 + off);
                mma8(acc[0][nt], a[0].x, a[1].x, a[0].y, a[1].y, bv.x, bv.y);
                mma8(acc[1][nt], a[2].x, a[3].x, a[2].y, a[3].y, bv.x, bv.y);
            }
        }
        __syncthreads();
    }

    const int m0 = mt0 * 64;
    #pragma unroll
    for (int mg = 0; mg < 2; mg++)
        #pragma unroll
        for (int j = 0; j < 2; j++) {
            const int m = m0 + ts * 64 + rA0 + 16 * mg + 8 * j;
            float* dst = out + (size_t)m * D_ + n0t * 64;
            #pragma unroll
            for (int nt = 0; nt < 8; nt++)
                *(float2*)(dst + nt * 8 + t * 2) =
                    make_float2(acc[mg][nt][2 * j], acc[mg][nt][2 * j + 1]);
        }
}

// ===========================================================================
// Flash attention: CTA = (b, h, 64 q-rows), 128 thr / 4 warps, 2 CTA/SM.
// smem words: buf0 [KHI 0 | KLO 4096 | VT 8192], buf1 +12288, PS 24576
// Total 28672 words = 112 KB -> 2 CTAs/SM (224 KB).
// ===========================================================================
#define ABUF 12288
#define APS  24576
#define ASMEM_WORDS 28672   // 112 KB

__global__ void __launch_bounds__(128, 2) attn_mma_kernel()
{
    extern __shared__ uint32_t smw[];
    const uint32_t sbase = smem_u32(smw);

    const int tid  = threadIdx.x;
    const int lane = tid & 31;
    const int w    = tid >> 5;            // 0..3
    const int g    = lane >> 2;
    const int t    = lane & 3;
    const int g2   = (g >> 2) & 1;
    const int row0 = w * 16 + g;          // 0..63
    const int offA = 2 * t ^ (4 * g2);
    const int pe = ((2 * t) & 3) * 2 + (t >> 1);
    const int po = ((2 * t + 1) & 3) * 2 + ((2 * t + 1) >> 2);

    const int h  = blockIdx.y;
    const int b  = blockIdx.z;
    const size_t kvbase = ((size_t)(b * H_ + h)) * 32 * 4096;

    // prologue: tile 0 into buf 0 (12288 words = 3072 cp16, 24/thread)
    {
        const uint4* sK = (const uint4*)(g_Khi + kvbase);
        const uint4* sL = (const uint4*)(g_Klo + kvbase);
        const uint4* sV = (const uint4*)(g_Vt  + kvbase);
        #pragma unroll
        for (int k = 0; k < 8; k++) {
            const int i = tid + k * 128;
            cp16(sbase + i * 16,          sK + i);
            cp16(sbase + 16384 + i * 16,  sL + i);
            cp16(sbase + 32768 + i * 16,  sV + i);
        }
        CP_COMMIT();
    }

    // Q fragments from preformatted kfmt tiles (qst = blockIdx.x)
    uint2 qh0[8], qh1[8], ql0[8], ql1[8];
    {
        const size_t qtb = ((size_t)(b * H_ + h) * 32 + blockIdx.x) * 4096;
        #pragma unroll
        for (int ks = 0; ks < 8; ks++) {
            const int off = offA ^ (4 * ((ks >> 2) & 1));
            const size_t i0 = qtb + (ks * 64 + row0) * 8 + off;
            const size_t i1 = qtb + (ks * 64 + row0 + 8) * 8 + off;
            qh0[ks] = *(const uint2*)(g_Qhi + i0);
            qh1[ks] = *(const uint2*)(g_Qhi + i1);
            ql0[ks] = *(const uint2*)(g_Qlo + i0);
            ql1[ks] = *(const uint2*)(g_Qlo + i1);
        }
    }

    float o[8][4];
    #pragma unroll
    for (int nt = 0; nt < 8; nt++)
        #pragma unroll
        for (int j = 0; j < 4; j++) o[nt][j] = 0.f;
    float mrun[2] = {-1e30f, -1e30f}, lrun[2] = {0.f, 0.f};
    const float Cc = 0.125f * 1.4426950408889634f;

    for (int it = 0; it < 32; it++) {
        const int cur = it & 1;

        if (it < 31) {
            const uint32_t db = sbase + (cur ^ 1) * (ABUF * 4);
            const size_t tb = kvbase + (size_t)(it + 1) * 4096;
            const uint4* sK = (const uint4*)(g_Khi + tb);
            const uint4* sL = (const uint4*)(g_Klo + tb);
            const uint4* sV = (const uint4*)(g_Vt  + tb);
            #pragma unroll
            for (int k = 0; k < 8; k++) {
                const int i = tid + k * 128;
                cp16(db + i * 16,          sK + i);
                cp16(db + 16384 + i * 16,  sL + i);
                cp16(db + 32768 + i * 16,  sV + i);
            }
            CP_COMMIT();
            asm volatile("cp.async.wait_group 1;" ::: "memory");
        } else {
            asm volatile("cp.async.wait_group 0;" ::: "memory");
        }
        __syncthreads();

        const int bk = cur * ABUF;

        // --- QK: split tf32 (3 terms) ---
        float accS[8][4];
        #pragma unroll
        for (int nt = 0; nt < 8; nt++)
            #pragma unroll
            for (int j = 0; j < 4; j++) accS[nt][j] = 0.f;

        #pragma unroll
        for (int ks = 0; ks < 8; ks++) {
            const int off = offA ^ (4 * ((ks >> 2) & 1));
            #pragma unroll
            for (int nt = 0; nt < 8; nt++) {
                const uint32_t ba = (uint32_t)(bk + (ks * 64 + nt * 8 + g) * 8 + off);
                uint2 bh = *(const uint2*)(smw + ba);
                uint2 bl = *(const uint2*)(smw + 4096 + ba);
                mma8(accS[nt], qh0[ks].x, qh1[ks].x, qh0[ks].y, qh1[ks].y, bh.x, bh.y);
                mma8(accS[nt], ql0[ks].x, ql1[ks].x, ql0[ks].y, ql1[ks].y, bh.x, bh.y);
                mma8(accS[nt], qh0[ks].x, qh1[ks].x, qh0[ks].y, qh1[ks].y, bl.x, bl.y);
            }
        }

        // --- Online softmax; write P (kfmt) into shared PS (rows disjoint/warp)
        #pragma unroll
        for (int j = 0; j < 2; j++) {
            float m = -1e30f;
            #pragma unroll
            for (int nt = 0; nt < 8; nt++)
                m = fmaxf(m, fmaxf(accS[nt][2 * j], accS[nt][2 * j + 1]));
            m = fmaxf(m, __shfl_xor_sync(0xffffffffu, m, 1));
            m = fmaxf(m, __shfl_xor_sync(0xffffffffu, m, 2));

            float mnew = fmaxf(mrun[j], m);
            float scl  = exp2f((mrun[j] - mnew) * Cc);
            mrun[j] = mnew;

            const int prow = row0 + 8 * j;
            float sum = 0.f;
            #pragma unroll
            for (int nt = 0; nt < 8; nt++) {
                float p0 = exp2f((accS[nt][2 * j]     - mnew) * Cc);
                float p1 = exp2f((accS[nt][2 * j + 1] - mnew) * Cc);
                sum += p0 + p1;
                const int sw = 4 * ((g2 ^ (nt >> 2)) & 1);
                const uint32_t base = (uint32_t)(APS + (nt * 64 + prow) * 8);
                smw[base + (pe ^ sw)] = f2tf32(p0);
                smw[base + (po ^ sw)] = f2tf32(p1);
                o[nt][2 * j]     *= scl;
                o[nt][2 * j + 1] *= scl;
            }
            sum += __shfl_xor_sync(0xffffffffu, sum, 1);
            sum += __shfl_xor_sync(0xffffffffu, sum, 2);
            lrun[j] = lrun[j] * scl + sum;
        }
        __syncwarp();

        // --- PV: O += P @ Vt (single tf32) ---
        #pragma unroll
        for (int ks = 0; ks < 8; ks++) {
            const int off = offA ^ (4 * ((ks >> 2) & 1));
            uint2 p0 = *(const uint2*)(smw + APS + (ks * 64 + row0) * 8 + off);
            uint2 p1 = *(const uint2*)(smw + APS + (ks * 64 + row0 + 8) * 8 + off);
            #pragma unroll
            for (int nt = 0; nt < 8; nt++) {
                uint2 bv = *(const uint2*)(smw + bk + 8192 + (ks * 64 + nt * 8 + g) * 8 + off);
                mma8(o[nt], p0.x, p1.x, p0.y, p1.y, bv.x, bv.y);
            }
        }
        __syncthreads();
    }

    // --- Epilogue: normalize, write kfmt tf32 tile into g_OcT ---
    {
        #pragma unroll
        for (int j = 0; j < 2; j++) {
            const float inv = 1.f / lrun[j];
            const int rr = row0 + 8 * j;
            #pragma unroll
            for (int nt = 0; nt < 8; nt++) {
                const int sw = 4 * (g2 ^ ((nt >> 2) & 1));
                const uint32_t base = (uint32_t)(APS + (nt * 64 + rr) * 8);
                smw[base + (pe ^ sw)] = f2tf32(o[nt][2 * j] * inv);
                smw[base + (po ^ sw)] = f2tf32(o[nt][2 * j + 1] * inv);
            }
        }
        __syncthreads();
        const int mt = b * 32 + blockIdx.x;
        uint32_t* d0 = g_OcT + ((size_t)mt * 8 + h) * 4096;
        const uint4* s4 = (const uint4*)(smw + APS);
        for (int i = tid; i < 1024; i += 128)
            ((uint4*)d0)[i] = s4[i];
    }
}

// ---------------------------------------------------------------------------
extern "C" void kernel_launch(void* const* d_in, const int* in_sizes, int n_in,
                              void* d_out, int out_size)
{
    const float* Q  = (const float*)d_in[0];
    const float* K  = (const float*)d_in[1];
    const float* V  = (const float*)d_in[2];
    const float* WQ = (const float*)d_in[3];
    const float* WK = (const float*)d_in[4];
    const float* WV = (const float*)d_in[5];
    const float* WO = (const float*)d_in[6];
    float* out = (float*)d_out;

    const size_t smemP = (size_t)PR_WORDS * 4;     // 96 KB
    const size_t smemO = (size_t)OG_WORDS * 4;     // 160 KB
    const size_t smemA = (size_t)ASMEM_WORDS * 4;  // 112 KB
    cudaFuncSetAttribute(proj_mma_kernel, cudaFuncAttributeMaxDynamicSharedMemorySize, (int)smemP);
    cudaFuncSetAttribute(out_mma_kernel,  cudaFuncAttributeMaxDynamicSharedMemorySize, (int)smemO);
    cudaFuncSetAttribute(attn_mma_kernel, cudaFuncAttributeMaxDynamicSharedMemorySize, (int)smemA);

    prep_w_kernel<<<dim3(8, 8, 4), 128>>>(WQ, WK, WV, WO);

    proj_mma_kernel<<<dim3(H_, (B_ * S_) / 64, 3), 128, smemP>>>(Q, K, V);

    attn_mma_kernel<<<dim3(S_ / 64, H_, B_), 128, smemA>>>();

    out_mma_kernel<<<dim3(8, (B_ * S_) / 256), 256, smemO>>>(out);
}

// round 14
// speedup vs baseline: 1.2871x; 1.1179x over previous
#include <cuda_runtime.h>
#include <cstdint>

#define B_   4
#define S_   2048
#define D_   512
#define H_   8
#define DK_  64

// ---------------------------------------------------------------------------
// Scratch (allocation-free: __device__ globals)
// ---------------------------------------------------------------------------
__device__ uint32_t g_Qhi[B_*H_*S_*DK_];   // [(b*H+h)*32 + stile][4096]
__device__ uint32_t g_Qlo[B_*H_*S_*DK_];
__device__ uint32_t g_Khi[B_*H_*S_*DK_];
__device__ uint32_t g_Klo[B_*H_*S_*DK_];
__device__ uint32_t g_Vt [B_*H_*S_*DK_];   // transposed (rows = dk, k = s)
__device__ uint32_t g_OcT[B_*S_*D_];       // attn out kfmt: [mtile(64)*8 + kchunk][4096]
__device__ uint32_t g_Whi[3*8*8*4096];     // [(which*8+h)*8 + c][4096]
__device__ uint32_t g_Wlo[3*8*8*4096];
__device__ uint32_t g_WOt[8*8*4096];       // [c*8 + ntile][4096]
__device__ uint32_t g_Xhi[3*128*8*4096];   // [(which*128+mt)*8 + c][4096]
__device__ uint32_t g_Xlo[3*128*8*4096];

// ===========================================================================
// mma.sync tf32 helpers (baseline PTX, works on compute_103 target)
// ===========================================================================
__device__ __forceinline__ uint32_t f2tf32(float x) {
    uint32_t r; asm("cvt.rna.tf32.f32 %0, %1;" : "=r"(r) : "f"(x)); return r;
}
__device__ __forceinline__ void mma8(float* d,
                                     uint32_t a0, uint32_t a1, uint32_t a2, uint32_t a3,
                                     uint32_t b0, uint32_t b1) {
    asm volatile("mma.sync.aligned.m16n8k8.row.col.f32.tf32.tf32.f32 "
                 "{%0,%1,%2,%3}, {%4,%5,%6,%7}, {%8,%9}, {%0,%1,%2,%3};"
                 : "+f"(d[0]), "+f"(d[1]), "+f"(d[2]), "+f"(d[3])
                 : "r"(a0), "r"(a1), "r"(a2), "r"(a3), "r"(b0), "r"(b1));
}
__device__ __forceinline__ void cp16(uint32_t saddr, const void* g) {
    asm volatile("cp.async.cg.shared.global [%0], [%1], 16;" :: "r"(saddr), "l"(g) : "memory");
}
#define CP_COMMIT() asm volatile("cp.async.commit_group;" ::: "memory")
__device__ __forceinline__ uint32_t smem_u32(const void* p) {
    uint32_t a;
    asm("{ .reg .u64 t; cvta.to.shared.u64 t, %1; cvt.u32.u64 %0, t; }" : "=r"(a) : "l"(p));
    return a;
}

// kfmt, per 64x64 tile: word(row,k) = (ks*64+row)*8 + pos(kin)^sw,
//   ks=k>>3, kin=k&7, pos(kin) = (kin&3)*2 + (kin>>2),
//   sw = 4*(((row>>2)^(ks>>2))&1). Fragment (kin=t,t+4) = LDS.64 at 2t^sw.

// ---------------------------------------------------------------------------
// Loaders (prep kernels)
// ---------------------------------------------------------------------------
__device__ __forceinline__ void ldg_rows(const float* __restrict__ src, int tid,
                                         int stride, float4 xa[4], float4 xb[4])
{
    const int r = tid >> 1, kh = tid & 1;
    #pragma unroll
    for (int j = 0; j < 4; j++) {
        const int ks = kh * 4 + j;
        xa[j] = *(const float4*)(src + (size_t)r * stride + ks * 8);
        xb[j] = *(const float4*)(src + (size_t)r * stride + ks * 8 + 4);
    }
}
__device__ __forceinline__ void sts_split(const float4 xa[4], const float4 xb[4],
                                          uint32_t* __restrict__ smw,
                                          int whi, int wlo, int tid)
{
    const int r = tid >> 1, kh = tid & 1;
    #pragma unroll
    for (int j = 0; j < 4; j++) {
        const int ks = kh * 4 + j;
        float x[8] = {xa[j].x, xa[j].y, xa[j].z, xa[j].w,
                      xb[j].x, xb[j].y, xb[j].z, xb[j].w};
        uint32_t h[8], l[8];
        #pragma unroll
        for (int e = 0; e < 8; e++) {
            h[e] = __float_as_uint(x[e]) & 0xFFFFE000u;
            l[e] = f2tf32(x[e] - __uint_as_float(h[e]));
        }
        const int sw = 4 * (((r >> 2) ^ (ks >> 2)) & 1);
        const uint32_t base = (uint32_t)((ks * 64 + r) * 8);
        *(uint4*)(smw + whi + base + (0 ^ sw)) = make_uint4(h[0], h[4], h[1], h[5]);
        *(uint4*)(smw + whi + base + (4 ^ sw)) = make_uint4(h[2], h[6], h[3], h[7]);
        *(uint4*)(smw + wlo + base + (0 ^ sw)) = make_uint4(l[0], l[4], l[1], l[5]);
        *(uint4*)(smw + wlo + base + (4 ^ sw)) = make_uint4(l[2], l[6], l[3], l[7]);
    }
}
__device__ __forceinline__ void ldg_T(const float* __restrict__ bsrc, int ldb,
                                      int tid, float wst[4][8])
{
    const int n = tid & 63, kh = tid >> 6;
    #pragma unroll
    for (int j = 0; j < 4; j++) {
        const int ks = kh * 4 + j;
        #pragma unroll
        for (int si = 0; si < 8; si++)
            wst[j][si] = bsrc[(size_t)(ks * 8 + si) * ldb + n];
    }
}
__device__ __forceinline__ void sts_T_split(const float wst[4][8],
                                            uint32_t* __restrict__ smw,
                                            int whi, int wlo, int tid)
{
    const int n = tid & 63, kh = tid >> 6;
    #pragma unroll
    for (int j = 0; j < 4; j++) {
        const int ks = kh * 4 + j;
        uint32_t h[8], l[8];
        #pragma unroll
        for (int e = 0; e < 8; e++) {
            h[e] = __float_as_uint(wst[j][e]) & 0xFFFFE000u;
            l[e] = f2tf32(wst[j][e] - __uint_as_float(h[e]));
        }
        const int sw = 4 * (((n >> 2) ^ (ks >> 2)) & 1);
        const uint32_t base = (uint32_t)((ks * 64 + n) * 8);
        *(uint4*)(smw + whi + base + (0 ^ sw)) = make_uint4(h[0], h[4], h[1], h[5]);
        *(uint4*)(smw + whi + base + (4 ^ sw)) = make_uint4(h[2], h[6], h[3], h[7]);
        *(uint4*)(smw + wlo + base + (0 ^ sw)) = make_uint4(l[0], l[4], l[1], l[5]);
        *(uint4*)(smw + wlo + base + (4 ^ sw)) = make_uint4(l[2], l[6], l[3], l[7]);
    }
}
__device__ __forceinline__ void sts_T_single(const float wst[4][8],
                                             uint32_t* __restrict__ smw,
                                             int whi, int tid)
{
    const int n = tid & 63, kh = tid >> 6;
    #pragma unroll
    for (int j = 0; j < 4; j++) {
        const int ks = kh * 4 + j;
        uint32_t h[8];
        #pragma unroll
        for (int e = 0; e < 8; e++) h[e] = f2tf32(wst[j][e]);
        const int sw = 4 * (((n >> 2) ^ (ks >> 2)) & 1);
        const uint32_t base = (uint32_t)((ks * 64 + n) * 8);
        *(uint4*)(smw + whi + base + (0 ^ sw)) = make_uint4(h[0], h[4], h[1], h[5]);
        *(uint4*)(smw + whi + base + (4 ^ sw)) = make_uint4(h[2], h[6], h[3], h[7]);
    }
}

// ===========================================================================
// prep_w: preformat weights into kfmt. grid (8, 8, 4), 128 thr.
// ===========================================================================
__global__ __launch_bounds__(128) void prep_w_kernel(const float* __restrict__ WQ,
                                                     const float* __restrict__ WK,
                                                     const float* __restrict__ WV,
                                                     const float* __restrict__ WO)
{
    __shared__ uint32_t smw[8192];
    const int tid = threadIdx.x;
    const int c  = blockIdx.x;
    const int hn = blockIdx.y;
    const int which = blockIdx.z;
    float wst[4][8];
    if (which < 3) {
        const float* W = (which == 0) ? WQ : (which == 1) ? WK : WV;
        const float* src = W + (size_t)hn * (D_ * DK_) + (size_t)c * 64 * DK_;
        ldg_T(src, DK_, tid, wst);
        sts_T_split(wst, smw, 0, 4096, tid);
        __syncthreads();
        uint32_t* dH = g_Whi + ((size_t)(which * 8 + hn) * 8 + c) * 4096;
        uint32_t* dL = g_Wlo + ((size_t)(which * 8 + hn) * 8 + c) * 4096;
        for (int i = tid; i < 1024; i += 128) {
            ((uint4*)dH)[i] = ((const uint4*)smw)[i];
            ((uint4*)dL)[i] = ((const uint4*)smw)[1024 + i];
        }
    } else {
        const float* src = WO + (size_t)c * 64 * D_ + hn * 64;
        ldg_T(src, D_, tid, wst);
        sts_T_single(wst, smw, 0, tid);
        __syncthreads();
        uint32_t* dW = g_WOt + ((size_t)(c * 8 + hn)) * 4096;
        for (int i = tid; i < 1024; i += 128)
            ((uint4*)dW)[i] = ((const uint4*)smw)[i];
    }
}

// ===========================================================================
// prep_x: preformat inputs into split hi/lo kfmt. grid (128, 3), 128 thr.
// ===========================================================================
__global__ __launch_bounds__(128) void prep_x_kernel(const float* __restrict__ Qx,
                                                     const float* __restrict__ Kx,
                                                     const float* __restrict__ Vx)
{
    __shared__ uint32_t smw[8192];
    const int tid = threadIdx.x;
    const int mt = blockIdx.x;
    const int which = blockIdx.y;
    const float* __restrict__ X = (which == 0) ? Qx : (which == 1) ? Kx : Vx;
    const float* __restrict__ Xm = X + (size_t)mt * 64 * D_;

    for (int c = 0; c < 8; c++) {
        float4 xa[4], xb[4];
        ldg_rows(Xm + c * 64, tid, D_, xa, xb);
        __syncthreads();                    // protect previous copy reads
        sts_split(xa, xb, smw, 0, 4096, tid);
        __syncthreads();
        uint32_t* dH = g_Xhi + ((size_t)(which * 128 + mt) * 8 + c) * 4096;
        uint32_t* dL = g_Xlo + ((size_t)(which * 128 + mt) * 8 + c) * 4096;
        for (int i = tid; i < 1024; i += 128) {
            ((uint4*)dH)[i] = ((const uint4*)smw)[i];
            ((uint4*)dL)[i] = ((const uint4*)smw)[1024 + i];
        }
    }
}

// ===========================================================================
// Projection GEMM: pure preformatted streaming, half-chunks (k=32).
// m-tile 64, 128 thr / 4 warps, m16/warp, split (3-term) for all 3.
// smem: 2 buffers x [Ahi 2048 | Alo 2048 | Bhi 2048 | Blo 2048] = 16384 w = 64 KB
// grid = (H, 128 m-tiles, 3).
// ===========================================================================
#define PR_WORDS 16384   // 64 KB

__global__ void __launch_bounds__(128, 3) proj_mma_kernel()
{
    extern __shared__ uint32_t smw[];
    const uint32_t sbase = smem_u32(smw);

    const int which = blockIdx.z;
    const int h  = blockIdx.x;
    const int mt = blockIdx.y;

    const int tid  = threadIdx.x;
    const int lane = tid & 31;
    const int w    = tid >> 5;
    const int g    = lane >> 2;
    const int t    = lane & 3;
    const int g2   = (g >> 2) & 1;
    const int row0 = w * 16 + g;
    const int pe = ((2 * t) & 3) * 2 + (t >> 1);
    const int po = ((2 * t + 1) & 3) * 2 + ((2 * t + 1) >> 2);

    const uint32_t* __restrict__ Ah = g_Xhi + (size_t)(which * 128 + mt) * 8 * 4096;
    const uint32_t* __restrict__ Al = g_Xlo + (size_t)(which * 128 + mt) * 8 * 4096;
    const uint32_t* __restrict__ Bh = g_Whi + (size_t)(which * 8 + h) * 8 * 4096;
    const uint32_t* __restrict__ Bl = g_Wlo + (size_t)(which * 8 + h) * 8 * 4096;

    float acc[8][4];
    #pragma unroll
    for (int nt = 0; nt < 8; nt++)
        #pragma unroll
        for (int j = 0; j < 4; j++) acc[nt][j] = 0.f;

    // half-chunk hc: chunk c = hc>>1, half = hc&1 (words half*2048 within tile)
    auto stage = [&](int hc, int buf) {
        const size_t toff = (size_t)(hc >> 1) * 4096 + (hc & 1) * 2048;
        const uint32_t db = sbase + (buf * 8192) * 4;
        const uint4* a0 = (const uint4*)(Ah + toff);
        const uint4* a1 = (const uint4*)(Al + toff);
        const uint4* b0 = (const uint4*)(Bh + toff);
        const uint4* b1 = (const uint4*)(Bl + toff);
        #pragma unroll
        for (int i = 0; i < 4; i++) {
            const int idx = tid + i * 128;               // 512 uint4 per region
            cp16(db + idx * 16,             a0 + idx);
            cp16(db + 2048 * 4 + idx * 16,  a1 + idx);
            cp16(db + 4096 * 4 + idx * 16,  b0 + idx);
            cp16(db + 6144 * 4 + idx * 16,  b1 + idx);
        }
        CP_COMMIT();
    };

    stage(0, 0);

    for (int hc = 0; hc < 16; hc++) {
        const int bb = hc & 1;
        if (hc < 15) {
            stage(hc + 1, bb ^ 1);
            asm volatile("cp.async.wait_group 1;" ::: "memory");
        } else {
            asm volatile("cp.async.wait_group 0;" ::: "memory");
        }
        __syncthreads();

        const uint32_t bw = bb * 8192;
        const int kspar = hc & 1;            // global (ks>>2) parity of this half
        #pragma unroll
        for (int ks = 0; ks < 4; ks++) {
            const int off = 2 * t ^ (4 * (g2 ^ kspar));
            const uint32_t ra0 = bw + (ks * 64 + row0) * 8 + off;
            const uint32_t ra1 = bw + (ks * 64 + row0 + 8) * 8 + off;
            uint2 ah0 = *(const uint2*)(smw + ra0);
            uint2 ah1 = *(const uint2*)(smw + ra1);
            uint2 al0 = *(const uint2*)(smw + 2048 + ra0);
            uint2 al1 = *(const uint2*)(smw + 2048 + ra1);
            #pragma unroll
            for (int nt = 0; nt < 8; nt++) {
                const uint32_t ba = bw + 4096 + (ks * 64 + nt * 8 + g) * 8 + off;
                uint2 bhv = *(const uint2*)(smw + ba);
                uint2 blv = *(const uint2*)(smw + 2048 + ba);
                mma8(acc[nt], ah0.x, ah1.x, ah0.y, ah1.y, bhv.x, bhv.y);
                mma8(acc[nt], al0.x, al1.x, al0.y, al1.y, bhv.x, bhv.y);
                mma8(acc[nt], ah0.x, ah1.x, ah0.y, ah1.y, blv.x, blv.y);
            }
        }
        __syncthreads();
    }

    const int m0 = mt * 64;
    const int bb2 = m0 >> 11;
    const int st0 = (m0 & 2047) >> 6;
    const size_t tbase = ((size_t)((bb2 * H_ + h) * 32 + st0)) * 4096;

    if (which != 2) {
        // --- Q/K epilogue: split kfmt staged in smem, then linear copy ---
        #pragma unroll
        for (int j = 0; j < 2; j++) {
            const int r = row0 + 8 * j;
            #pragma unroll
            for (int nt = 0; nt < 8; nt++) {
                float p0 = acc[nt][2 * j], p1 = acc[nt][2 * j + 1];
                uint32_t h0 = __float_as_uint(p0) & 0xFFFFE000u;
                uint32_t h1 = __float_as_uint(p1) & 0xFFFFE000u;
                uint32_t l0 = f2tf32(p0 - __uint_as_float(h0));
                uint32_t l1 = f2tf32(p1 - __uint_as_float(h1));
                const int sw = 4 * ((((r >> 2) ^ (nt >> 2)) & 1));
                const uint32_t base = (uint32_t)((nt * 64 + r) * 8);
                smw[base + (pe ^ sw)] = h0;
                smw[base + (po ^ sw)] = h1;
                smw[4096 + base + (pe ^ sw)] = l0;
                smw[4096 + base + (po ^ sw)] = l1;
            }
        }
        __syncthreads();
        uint32_t* dH = (which == 0 ? g_Qhi : g_Khi) + tbase;
        uint32_t* dL = (which == 0 ? g_Qlo : g_Klo) + tbase;
        const uint4* s4 = (const uint4*)smw;
        for (int i = tid; i < 1024; i += 128) {
            ((uint4*)dH)[i] = s4[i];
            ((uint4*)dL)[i] = s4[1024 + i];
        }
    } else {
        // --- V epilogue: raw tf32 stage -> transpose -> kfmt Vt ---
        #pragma unroll
        for (int j = 0; j < 2; j++) {
            const int r = row0 + 8 * j;
            #pragma unroll
            for (int nt = 0; nt < 8; nt++) {
                smw[r * 64 + nt * 8 + 2 * t]     = f2tf32(acc[nt][2 * j]);
                smw[r * 64 + nt * 8 + 2 * t + 1] = f2tf32(acc[nt][2 * j + 1]);
            }
        }
        __syncthreads();
        {
            const int vdk = tid & 63, vsh = tid >> 6;
            #pragma unroll
            for (int j = 0; j < 4; j++) {
                const int sc = vsh * 4 + j;
                uint32_t v[8];
                #pragma unroll
                for (int si = 0; si < 8; si++)
                    v[si] = smw[(sc * 8 + si) * 64 + vdk];
                const int sw = 4 * (((vdk >> 2) ^ (sc >> 2)) & 1);
                const uint32_t base = (uint32_t)((sc * 64 + vdk) * 8);
                *(uint4*)(smw + 4096 + base + (0 ^ sw)) = make_uint4(v[0], v[4], v[1], v[5]);
                *(uint4*)(smw + 4096 + base + (4 ^ sw)) = make_uint4(v[2], v[6], v[3], v[7]);
            }
        }
        __syncthreads();
        uint32_t* dV = g_Vt + tbase;
        const uint4* s4 = (const uint4*)(smw + 4096);
        for (int i = tid; i < 1024; i += 128)
            ((uint4*)dV)[i] = s4[i];
    }
}

// ===========================================================================
// Output GEMM: pure preformatted streaming, m-tile 64, 128 thr, single tf32.
// smem: 2 buffers x [A 4096 | B 4096] = 16384 words = 64 KB. grid (8, 128).
// ===========================================================================
#define OG_WORDS 16384   // 64 KB

__global__ void __launch_bounds__(128, 3) out_mma_kernel(float* __restrict__ out)
{
    extern __shared__ uint32_t smw[];
    const uint32_t sbase = smem_u32(smw);

    const int tid  = threadIdx.x;
    const int lane = tid & 31;
    const int w    = tid >> 5;
    const int g    = lane >> 2;
    const int t    = lane & 3;
    const int g2   = (g >> 2) & 1;
    const int row0 = w * 16 + g;

    const int n0t = blockIdx.x;
    const int mt  = blockIdx.y;

    float acc[8][4];
    #pragma unroll
    for (int nt = 0; nt < 8; nt++)
        #pragma unroll
        for (int j = 0; j < 4; j++) acc[nt][j] = 0.f;

    auto stage = [&](int c, int buf) {
        const uint4* sa = (const uint4*)(g_OcT + ((size_t)mt * 8 + c) * 4096);
        const uint4* sb = (const uint4*)(g_WOt + ((size_t)(c * 8 + n0t)) * 4096);
        const uint32_t db = sbase + (buf * 8192) * 4;
        #pragma unroll
        for (int i = 0; i < 8; i++) {
            const int idx = tid + i * 128;               // 1024 uint4 per region
            cp16(db + idx * 16,            sa + idx);
            cp16(db + 4096 * 4 + idx * 16, sb + idx);
        }
        CP_COMMIT();
    };

    stage(0, 0);

    for (int c = 0; c < 8; c++) {
        const int bb = c & 1;
        if (c < 7) {
            stage(c + 1, bb ^ 1);
            asm volatile("cp.async.wait_group 1;" ::: "memory");
        } else {
            asm volatile("cp.async.wait_group 0;" ::: "memory");
        }
        __syncthreads();

        const uint32_t bw = bb * 8192;
        #pragma unroll
        for (int ks = 0; ks < 8; ks++) {
            const int off = 2 * t ^ (4 * (g2 ^ ((ks >> 2) & 1)));
            uint2 a0 = *(const uint2*)(smw + bw + (ks * 64 + row0) * 8 + off);
            uint2 a1 = *(const uint2*)(smw + bw + (ks * 64 + row0 + 8) * 8 + off);
            #pragma unroll
            for (int nt = 0; nt < 8; nt++) {
                uint2 bv = *(const uint2*)(smw + bw + 4096 + (ks * 64 + nt * 8 + g) * 8 + off);
                mma8(acc[nt], a0.x, a1.x, a0.y, a1.y, bv.x, bv.y);
            }
        }
        __syncthreads();
    }

    const int m0 = mt * 64;
    #pragma unroll
    for (int j = 0; j < 2; j++) {
        const int m = m0 + row0 + 8 * j;
        float* dst = out + (size_t)m * D_ + n0t * 64;
        #pragma unroll
        for (int nt = 0; nt < 8; nt++)
            *(float2*)(dst + nt * 8 + t * 2) =
                make_float2(acc[nt][2 * j], acc[nt][2 * j + 1]);
    }
}

// ===========================================================================
// Flash attention (unchanged R13): CTA = (b, h, 64 q-rows), 128 thr, 2 CTA/SM.
// smem words: buf0 [KHI 0 | KLO 4096 | VT 8192], buf1 +12288, PS 24576
// ===========================================================================
#define ABUF 12288
#define APS  24576
#define ASMEM_WORDS 28672   // 112 KB

__global__ void __launch_bounds__(128, 2) attn_mma_kernel()
{
    extern __shared__ uint32_t smw[];
    const uint32_t sbase = smem_u32(smw);

    const int tid  = threadIdx.x;
    const int lane = tid & 31;
    const int w    = tid >> 5;
    const int g    = lane >> 2;
    const int t    = lane & 3;
    const int g2   = (g >> 2) & 1;
    const int row0 = w * 16 + g;
    const int offA = 2 * t ^ (4 * g2);
    const int pe = ((2 * t) & 3) * 2 + (t >> 1);
    const int po = ((2 * t + 1) & 3) * 2 + ((2 * t + 1) >> 2);

    const int h  = blockIdx.y;
    const int b  = blockIdx.z;
    const size_t kvbase = ((size_t)(b * H_ + h)) * 32 * 4096;

    {
        const uint4* sK = (const uint4*)(g_Khi + kvbase);
        const uint4* sL = (const uint4*)(g_Klo + kvbase);
        const uint4* sV = (const uint4*)(g_Vt  + kvbase);
        #pragma unroll
        for (int k = 0; k < 8; k++) {
            const int i = tid + k * 128;
            cp16(sbase + i * 16,          sK + i);
            cp16(sbase + 16384 + i * 16,  sL + i);
            cp16(sbase + 32768 + i * 16,  sV + i);
        }
        CP_COMMIT();
    }

    uint2 qh0[8], qh1[8], ql0[8], ql1[8];
    {
        const size_t qtb = ((size_t)(b * H_ + h) * 32 + blockIdx.x) * 4096;
        #pragma unroll
        for (int ks = 0; ks < 8; ks++) {
            const int off = offA ^ (4 * ((ks >> 2) & 1));
            const size_t i0 = qtb + (ks * 64 + row0) * 8 + off;
            const size_t i1 = qtb + (ks * 64 + row0 + 8) * 8 + off;
            qh0[ks] = *(const uint2*)(g_Qhi + i0);
            qh1[ks] = *(const uint2*)(g_Qhi + i1);
            ql0[ks] = *(const uint2*)(g_Qlo + i0);
            ql1[ks] = *(const uint2*)(g_Qlo + i1);
        }
    }

    float o[8][4];
    #pragma unroll
    for (int nt = 0; nt < 8; nt++)
        #pragma unroll
        for (int j = 0; j < 4; j++) o[nt][j] = 0.f;
    float mrun[2] = {-1e30f, -1e30f}, lrun[2] = {0.f, 0.f};
    const float Cc = 0.125f * 1.4426950408889634f;

    for (int it = 0; it < 32; it++) {
        const int cur = it & 1;

        if (it < 31) {
            const uint32_t db = sbase + (cur ^ 1) * (ABUF * 4);
            const size_t tb = kvbase + (size_t)(it + 1) * 4096;
            const uint4* sK = (const uint4*)(g_Khi + tb);
            const uint4* sL = (const uint4*)(g_Klo + tb);
            const uint4* sV = (const uint4*)(g_Vt  + tb);
            #pragma unroll
            for (int k = 0; k < 8; k++) {
                const int i = tid + k * 128;
                cp16(db + i * 16,          sK + i);
                cp16(db + 16384 + i * 16,  sL + i);
                cp16(db + 32768 + i * 16,  sV + i);
            }
            CP_COMMIT();
            asm volatile("cp.async.wait_group 1;" ::: "memory");
        } else {
            asm volatile("cp.async.wait_group 0;" ::: "memory");
        }
        __syncthreads();

        const int bk = cur * ABUF;

        float accS[8][4];
        #pragma unroll
        for (int nt = 0; nt < 8; nt++)
            #pragma unroll
            for (int j = 0; j < 4; j++) accS[nt][j] = 0.f;

        #pragma unroll
        for (int ks = 0; ks < 8; ks++) {
            const int off = offA ^ (4 * ((ks >> 2) & 1));
            #pragma unroll
            for (int nt = 0; nt < 8; nt++) {
                const uint32_t ba = (uint32_t)(bk + (ks * 64 + nt * 8 + g) * 8 + off);
                uint2 bh = *(const uint2*)(smw + ba);
                uint2 bl = *(const uint2*)(smw + 4096 + ba);
                mma8(accS[nt], qh0[ks].x, qh1[ks].x, qh0[ks].y, qh1[ks].y, bh.x, bh.y);
                mma8(accS[nt], ql0[ks].x, ql1[ks].x, ql0[ks].y, ql1[ks].y, bh.x, bh.y);
                mma8(accS[nt], qh0[ks].x, qh1[ks].x, qh0[ks].y, qh1[ks].y, bl.x, bl.y);
            }
        }

        #pragma unroll
        for (int j = 0; j < 2; j++) {
            float m = -1e30f;
            #pragma unroll
            for (int nt = 0; nt < 8; nt++)
                m = fmaxf(m, fmaxf(accS[nt][2 * j], accS[nt][2 * j + 1]));
            m = fmaxf(m, __shfl_xor_sync(0xffffffffu, m, 1));
            m = fmaxf(m, __shfl_xor_sync(0xffffffffu, m, 2));

            float mnew = fmaxf(mrun[j], m);
            float scl  = exp2f((mrun[j] - mnew) * Cc);
            mrun[j] = mnew;

            const int prow = row0 + 8 * j;
            float sum = 0.f;
            #pragma unroll
            for (int nt = 0; nt < 8; nt++) {
                float p0 = exp2f((accS[nt][2 * j]     - mnew) * Cc);
                float p1 = exp2f((accS[nt][2 * j + 1] - mnew) * Cc);
                sum += p0 + p1;
                const int sw = 4 * ((g2 ^ (nt >> 2)) & 1);
                const uint32_t base = (uint32_t)(APS + (nt * 64 + prow) * 8);
                smw[base + (pe ^ sw)] = f2tf32(p0);
                smw[base + (po ^ sw)] = f2tf32(p1);
                o[nt][2 * j]     *= scl;
                o[nt][2 * j + 1] *= scl;
            }
            sum += __shfl_xor_sync(0xffffffffu, sum, 1);
            sum += __shfl_xor_sync(0xffffffffu, sum, 2);
            lrun[j] = lrun[j] * scl + sum;
        }
        __syncwarp();

        #pragma unroll
        for (int ks = 0; ks < 8; ks++) {
            const int off = offA ^ (4 * ((ks >> 2) & 1));
            uint2 p0 = *(const uint2*)(smw + APS + (ks * 64 + row0) * 8 + off);
            uint2 p1 = *(const uint2*)(smw + APS + (ks * 64 + row0 + 8) * 8 + off);
            #pragma unroll
            for (int nt = 0; nt < 8; nt++) {
                uint2 bv = *(const uint2*)(smw + bk + 8192 + (ks * 64 + nt * 8 + g) * 8 + off);
                mma8(o[nt], p0.x, p1.x, p0.y, p1.y, bv.x, bv.y);
            }
        }
        __syncthreads();
    }

    {
        #pragma unroll
        for (int j = 0; j < 2; j++) {
            const float inv = 1.f / lrun[j];
            const int rr = row0 + 8 * j;
            #pragma unroll
            for (int nt = 0; nt < 8; nt++) {
                const int sw = 4 * (g2 ^ ((nt >> 2) & 1));
                const uint32_t base = (uint32_t)(APS + (nt * 64 + rr) * 8);
                smw[base + (pe ^ sw)] = f2tf32(o[nt][2 * j] * inv);
                smw[base + (po ^ sw)] = f2tf32(o[nt][2 * j + 1] * inv);
            }
        }
        __syncthreads();
        const int mt = b * 32 + blockIdx.x;
        uint32_t* d0 = g_OcT + ((size_t)mt * 8 + h) * 4096;
        const uint4* s4 = (const uint4*)(smw + APS);
        for (int i = tid; i < 1024; i += 128)
            ((uint4*)d0)[i] = s4[i];
    }
}

// ---------------------------------------------------------------------------
extern "C" void kernel_launch(void* const* d_in, const int* in_sizes, int n_in,
                              void* d_out, int out_size)
{
    const float* Q  = (const float*)d_in[0];
    const float* K  = (const float*)d_in[1];
    const float* V  = (const float*)d_in[2];
    const float* WQ = (const float*)d_in[3];
    const float* WK = (const float*)d_in[4];
    const float* WV = (const float*)d_in[5];
    const float* WO = (const float*)d_in[6];
    float* out = (float*)d_out;

    const size_t smemP = (size_t)PR_WORDS * 4;     // 64 KB
    const size_t smemO = (size_t)OG_WORDS * 4;     // 64 KB
    const size_t smemA = (size_t)ASMEM_WORDS * 4;  // 112 KB
    cudaFuncSetAttribute(proj_mma_kernel, cudaFuncAttributeMaxDynamicSharedMemorySize, (int)smemP);
    cudaFuncSetAttribute(out_mma_kernel,  cudaFuncAttributeMaxDynamicSharedMemorySize, (int)smemO);
    cudaFuncSetAttribute(attn_mma_kernel, cudaFuncAttributeMaxDynamicSharedMemorySize, (int)smemA);

    prep_w_kernel<<<dim3(8, 8, 4), 128>>>(WQ, WK, WV, WO);
    prep_x_kernel<<<dim3(128, 3), 128>>>(Q, K, V);

    proj_mma_kernel<<<dim3(H_, 128, 3), 128, smemP>>>();

    attn_mma_kernel<<<dim3(S_ / 64, H_, B_), 128, smemA>>>();

    out_mma_kernel<<<dim3(8, 128), 128, smemO>>>(out);
}